// round 8
// baseline (speedup 1.0000x reference)
#include <cuda_runtime.h>
#include <cuda_bf16.h>
#include <cstdint>
#include <stdint.h>
#include <math.h>

#define NMAX 8192
#define DMAX 128
#define NCLS 128

// Scratch (no cudaMalloc allowed)
__device__ float g_pos_min[NMAX];
__device__ float g_pos_sum[NMAX];
__device__ float g_neg_sum[NMAX];
__device__ float g_last[4];       // [0]=pos_cnt [1]=pos_simsum [2]=neg_cnt [3]=neg_simsum
__device__ int   g_cls_cnt[NCLS];
__device__ int   g_cls_off[NCLS + 1];
__device__ int   g_cls_cur[NCLS];
__device__ int   g_cls_list[NMAX];
__device__ __nv_bfloat16 g_xhi[NMAX * DMAX];
__device__ __nv_bfloat16 g_xlo[NMAX * DMAX];

// -----------------------------------------------------------------------------
// Setup kernels
// -----------------------------------------------------------------------------
__global__ void k_zero() {
    int i = threadIdx.x;
    if (i < NCLS) { g_cls_cnt[i] = 0; g_cls_cur[i] = 0; }
    if (i < 4) g_last[i] = 0.f;
}
__global__ void k_hist(const int* __restrict__ t, int n) {
    int i = blockIdx.x * blockDim.x + threadIdx.x;
    if (i < n) atomicAdd(&g_cls_cnt[t[i]], 1);
}
__global__ void k_scan() {
    if (threadIdx.x == 0) {
        int acc = 0;
        for (int c = 0; c < NCLS; c++) { g_cls_off[c] = acc; acc += g_cls_cnt[c]; }
        g_cls_off[NCLS] = acc;
    }
}
__global__ void k_scatter(const int* __restrict__ t, int n) {
    int i = blockIdx.x * blockDim.x + threadIdx.x;
    if (i < n) {
        int c = t[i];
        int p = atomicAdd(&g_cls_cur[c], 1);
        g_cls_list[g_cls_off[c] + p] = i;
    }
}
__global__ void k_split(const float* __restrict__ x, int total) {
    int i = blockIdx.x * blockDim.x + threadIdx.x;
    if (i < total) {
        float v = x[i];
        __nv_bfloat16 hi = __float2bfloat16(v);
        g_xhi[i] = hi;
        g_xlo[i] = __float2bfloat16(v - __bfloat162float(hi));
    }
}

// -----------------------------------------------------------------------------
// Kernel 1: class-blocked positive pass (exact fp32).
// One CTA per class; member rows cached in smem; warp-per-i, lane k-slices.
// -----------------------------------------------------------------------------
#define TJC 192

__global__ __launch_bounds__(256)
void pos_pass2(const float* __restrict__ x, int n) {
    int cls = blockIdx.x;
    int beg = g_cls_off[cls], end = g_cls_off[cls + 1];
    int cnt = end - beg;
    if (cnt <= 0) return;

    extern __shared__ float4 sj4[];   // TJC * 32 float4 = 96 KB
    int tid = threadIdx.x, lane = tid & 31, wrp = tid >> 5;
    const float4* X4 = (const float4*)x;

    bool fast = (cnt <= TJC);
    if (fast) {
        for (int idx = tid; idx < cnt * 32; idx += 256) {
            int r = idx >> 5, c = idx & 31;
            sj4[idx] = X4[(size_t)g_cls_list[beg + r] * 32 + c];
        }
    }
    __syncthreads();

    for (int mi = beg + wrp; mi < end; mi += 8) {
        int i = g_cls_list[mi];
        float4 xi = X4[(size_t)i * 32 + lane];
        float pmin = INFINITY, psum = 0.f, pcnt = 0.f, psim = 0.f;
        for (int mj = 0; mj < cnt; mj++) {
            float4 xj = fast ? sj4[mj * 32 + lane]
                             : X4[(size_t)g_cls_list[beg + mj] * 32 + lane];
            float p = xi.x * xj.x + xi.y * xj.y + xi.z * xj.z + xi.w * xj.w;
            p += __shfl_xor_sync(0xffffffffu, p, 16);
            p += __shfl_xor_sync(0xffffffffu, p, 8);
            p += __shfl_xor_sync(0xffffffffu, p, 4);
            p += __shfl_xor_sync(0xffffffffu, p, 2);
            p += __shfl_xor_sync(0xffffffffu, p, 1);
            if (p < 0.9f) {          // diagonal (p = 1.0) excluded
                pmin = fminf(pmin, p);
                float dm = p - 0.9f;
                psum += expf(-2.f * (p - 0.5f) + dm * dm);
                pcnt += 1.f;
                psim += p;
            }
        }
        if (lane == 0) {
            g_pos_min[i] = pmin;
            g_pos_sum[i] = psum;
            g_neg_sum[i] = 0.f;
            if (i == n - 1) { g_last[0] = pcnt; g_last[1] = psim; }
        }
    }
}

// -----------------------------------------------------------------------------
// Kernel 2: row-persistent pipelined HMMA (bf16-split) + symmetric epilogue.
// Grid (8, 64): CTA (c, ib) keeps A row-block resident, walks col tiles
// jt = ib+c, ib+c+8, ... with double-buffered cp.async B tiles.
// sim = hi*hi + hi*lo + lo*hi (fp32 accum).
// -----------------------------------------------------------------------------
#define BT   128
#define PAD  136                       // bf16 elements per padded smem row
#define ROWB (PAD * 2)                 // 272 bytes
#define TPADB (BT * ROWB)              // 34816 bytes per tile
#define NEG_SMEM (6 * TPADB)           // A hi/lo + 2x B hi/lo = 208896 B

__device__ __forceinline__ uint32_t smem_u32(const void* p) {
    uint32_t a;
    asm("{ .reg .u64 t; cvta.to.shared.u64 t, %1; cvt.u32.u64 %0, t; }"
        : "=r"(a) : "l"(p));
    return a;
}
__device__ __forceinline__ void cp_async16(uint32_t dst, const void* src) {
    asm volatile("cp.async.cg.shared.global [%0], [%1], 16;" :: "r"(dst), "l"(src));
}
__device__ __forceinline__ void mma16816(float* c, const unsigned* a, const unsigned* b) {
    asm volatile(
        "mma.sync.aligned.m16n8k16.row.col.f32.bf16.bf16.f32 "
        "{%0,%1,%2,%3}, {%4,%5,%6,%7}, {%8,%9}, {%0,%1,%2,%3};"
        : "+f"(c[0]), "+f"(c[1]), "+f"(c[2]), "+f"(c[3])
        : "r"(a[0]), "r"(a[1]), "r"(a[2]), "r"(a[3]), "r"(b[0]), "r"(b[1]));
}

// copy one 128x128 bf16 row-block (hi+lo) into padded smem tiles
__device__ __forceinline__ void copy_tile(uint32_t dstHi, uint32_t dstLo,
                                          int row0, int tid) {
    for (int idx = tid; idx < BT * 16; idx += 256) {
        int r = idx >> 4, ch = idx & 15;
        uint32_t off = (uint32_t)r * ROWB + (uint32_t)ch * 16u;
        const char* sh = (const char*)(g_xhi + (size_t)(row0 + r) * DMAX) + ch * 16;
        const char* sl = (const char*)(g_xlo + (size_t)(row0 + r) * DMAX) + ch * 16;
        cp_async16(dstHi + off, sh);
        cp_async16(dstLo + off, sl);
    }
}

__global__ __launch_bounds__(256, 1)
void neg_pass_mma(const int* __restrict__ t, int n) {
    int ib = blockIdx.y;                 // row-block 0..63
    int c  = blockIdx.x;                 // 0..7
    int ntiles = n / BT;                 // 64
    int jfirst = ib + c;
    if (jfirst >= ntiles) return;
    int i0 = ib * BT;

    extern __shared__ char dsm[];
    uint32_t base = smem_u32(dsm);
    uint32_t Ahi = base,              Alo = base + TPADB;
    uint32_t Bhi[2] = { base + 2 * TPADB, base + 4 * TPADB };
    uint32_t Blo[2] = { base + 3 * TPADB, base + 5 * TPADB };

    __shared__ float srow[BT], scol[BT], slast2[2];

    int tid  = threadIdx.x;
    int lane = tid & 31;
    int w    = tid >> 5;
    int wm   = w >> 2;                   // 0..1 -> 64-row half
    int wn   = w & 3;                    // 0..3 -> 32-col quarter
    int q    = lane >> 2;                // 0..7
    int tq   = lane & 3;                 // 0..3

    // zero shared accumulators
    if (tid < BT) { srow[tid] = 0.f; scol[tid] = 0.f; }
    if (tid < 2)  slast2[tid] = 0.f;

    // A resident + first B prefetch
    copy_tile(Ahi, Alo, i0, tid);
    copy_tile(Bhi[0], Blo[0], jfirst * BT, tid);
    asm volatile("cp.async.commit_group;" ::: "memory");
    asm volatile("cp.async.wait_group 0;" ::: "memory");

    // row-side labels / gates (constant across tiles)
    int   tti[8]; float tpmR[8];
    #pragma unroll
    for (int mf = 0; mf < 4; mf++)
        #pragma unroll
        for (int rh = 0; rh < 2; rh++) {
            int row = i0 + wm * 64 + mf * 16 + q + rh * 8;
            tti[mf * 2 + rh]  = t[row];
            tpmR[mf * 2 + rh] = g_pos_min[row];
        }
    bool iblast = (ib == ntiles - 1);

    int buf = 0;
    for (int jt = jfirst; jt < ntiles; jt += 8) {
        int j0 = jt * BT;
        bool offdiag = (jt > ib);
        bool more = (jt + 8 < ntiles);

        __syncthreads();   // B[buf] ready for all; srow/scol zeroed visible

        if (more) {
            copy_tile(Bhi[buf ^ 1], Blo[buf ^ 1], (jt + 8) * BT, tid);
            asm volatile("cp.async.commit_group;" ::: "memory");
        }

        // ---- MMA: 3 bf16-split products, A frags shared across Bhi/Blo ----
        float acc[4][4][4];
        #pragma unroll
        for (int mf = 0; mf < 4; mf++)
            #pragma unroll
            for (int nf = 0; nf < 4; nf++)
                #pragma unroll
                for (int r = 0; r < 4; r++) acc[mf][nf][r] = 0.f;

        const __nv_bfloat16* pAhi = (const __nv_bfloat16*)(dsm);
        const __nv_bfloat16* pAlo = (const __nv_bfloat16*)(dsm + TPADB);
        const __nv_bfloat16* pBhi = (const __nv_bfloat16*)(dsm + (2 + buf * 2) * TPADB);
        const __nv_bfloat16* pBlo = (const __nv_bfloat16*)(dsm + (3 + buf * 2) * TPADB);

        for (int kc = 0; kc < DMAX / 16; kc++) {
            int k0 = kc * 16;
            unsigned ah[4][4], al[4][4], bh[4][2], bl[4][2];
            #pragma unroll
            for (int mf = 0; mf < 4; mf++) {
                int r0 = wm * 64 + mf * 16 + q;
                const __nv_bfloat16* bse = pAhi + r0 * PAD + k0 + tq * 2;
                ah[mf][0] = *(const unsigned*)(bse);
                ah[mf][1] = *(const unsigned*)(bse + 8 * PAD);
                ah[mf][2] = *(const unsigned*)(bse + 8);
                ah[mf][3] = *(const unsigned*)(bse + 8 * PAD + 8);
                const __nv_bfloat16* bsl = pAlo + r0 * PAD + k0 + tq * 2;
                al[mf][0] = *(const unsigned*)(bsl);
                al[mf][1] = *(const unsigned*)(bsl + 8 * PAD);
                al[mf][2] = *(const unsigned*)(bsl + 8);
                al[mf][3] = *(const unsigned*)(bsl + 8 * PAD + 8);
            }
            #pragma unroll
            for (int nf = 0; nf < 4; nf++) {
                int c0 = wn * 32 + nf * 8 + q;
                const __nv_bfloat16* bse = pBhi + c0 * PAD + k0 + tq * 2;
                bh[nf][0] = *(const unsigned*)(bse);
                bh[nf][1] = *(const unsigned*)(bse + 8);
                const __nv_bfloat16* bsl = pBlo + c0 * PAD + k0 + tq * 2;
                bl[nf][0] = *(const unsigned*)(bsl);
                bl[nf][1] = *(const unsigned*)(bsl + 8);
            }
            #pragma unroll
            for (int mf = 0; mf < 4; mf++)
                #pragma unroll
                for (int nf = 0; nf < 4; nf++) {
                    mma16816(acc[mf][nf], ah[mf], bh[nf]);   // hi*hi
                    mma16816(acc[mf][nf], ah[mf], bl[nf]);   // hi*lo
                    mma16816(acc[mf][nf], al[mf], bh[nf]);   // lo*hi
                }
        }

        // ---- epilogue ----
        int   ttj[8]; float tpmC[8];
        #pragma unroll
        for (int nf = 0; nf < 4; nf++)
            #pragma unroll
            for (int cl = 0; cl < 2; cl++) {
                int col = j0 + wn * 32 + nf * 8 + tq * 2 + cl;
                ttj[nf * 2 + cl]  = t[col];
                tpmC[nf * 2 + cl] = g_pos_min[col];
            }

        float rsum[8], csum[8];
        #pragma unroll
        for (int k = 0; k < 8; k++) { rsum[k] = 0.f; csum[k] = 0.f; }

        #pragma unroll
        for (int mf = 0; mf < 4; mf++) {
            #pragma unroll
            for (int nf = 0; nf < 4; nf++) {
                #pragma unroll
                for (int r = 0; r < 4; r++) {
                    float s = acc[mf][nf][r];
                    int ri = mf * 2 + (r >> 1);
                    int ci = nf * 2 + (r & 1);
                    if (ttj[ci] != tti[ri] && s > 0.1f) {
                        float dm = 0.1f - s;
                        float e = __expf(50.f * (s - 0.5f) + dm * dm);
                        if (s + 0.5f > tpmR[ri]) {
                            rsum[ri] += e;
                            if (iblast) {
                                int row = i0 + wm * 64 + mf * 16 + q + (r >> 1) * 8;
                                if (row == n - 1) {
                                    atomicAdd(&slast2[0], 1.f);
                                    atomicAdd(&slast2[1], s);
                                }
                            }
                        }
                        if (offdiag && s + 0.5f > tpmC[ci]) {
                            csum[ci] += e;
                            if (jt == ntiles - 1) {
                                int col = j0 + wn * 32 + nf * 8 + tq * 2 + (r & 1);
                                if (col == n - 1) {
                                    atomicAdd(&slast2[0], 1.f);
                                    atomicAdd(&slast2[1], s);
                                }
                            }
                        }
                    }
                }
            }
        }

        // row sums: reduce over tq (xor 1,2)
        #pragma unroll
        for (int ri = 0; ri < 8; ri++) {
            float v = rsum[ri];
            v += __shfl_xor_sync(0xffffffffu, v, 1);
            v += __shfl_xor_sync(0xffffffffu, v, 2);
            if (tq == 0 && v != 0.f) {
                int mf = ri >> 1, rh = ri & 1;
                atomicAdd(&srow[wm * 64 + mf * 16 + q + rh * 8], v);
            }
        }
        // col sums: reduce over q (xor 4,8,16)
        if (offdiag) {
            #pragma unroll
            for (int ci = 0; ci < 8; ci++) {
                float v = csum[ci];
                v += __shfl_xor_sync(0xffffffffu, v, 4);
                v += __shfl_xor_sync(0xffffffffu, v, 8);
                v += __shfl_xor_sync(0xffffffffu, v, 16);
                if (q == 0 && v != 0.f) {
                    int nf = ci >> 1, cl = ci & 1;
                    atomicAdd(&scol[wn * 32 + nf * 8 + tq * 2 + cl], v);
                }
            }
        }
        __syncthreads();

        // flush + re-zero (same thread handles same element: no race)
        if (tid < BT) {
            if (srow[tid] != 0.f) atomicAdd(&g_neg_sum[i0 + tid], srow[tid]);
            if (offdiag && scol[tid] != 0.f) atomicAdd(&g_neg_sum[j0 + tid], scol[tid]);
            srow[tid] = 0.f; scol[tid] = 0.f;
        }
        if (tid == 0 && slast2[0] != 0.f) {
            atomicAdd(&g_last[2], slast2[0]);
            atomicAdd(&g_last[3], slast2[1]);
            slast2[0] = 0.f; slast2[1] = 0.f;
        }

        if (more)
            asm volatile("cp.async.wait_group 0;" ::: "memory");
        buf ^= 1;
    }
}

// -----------------------------------------------------------------------------
// Kernel 3: finalize
// -----------------------------------------------------------------------------
__global__ void finalize(float* __restrict__ out, int n) {
    __shared__ float shl[8], shp[8];
    int tid = threadIdx.x;
    float loss = 0.f, noneg = 0.f;
    for (int i = tid; i < n; i += blockDim.x) {
        float ns = g_neg_sum[i];
        if (ns > 0.f) {
            loss += 0.5f * log1pf(g_pos_sum[i]) + (1.f / 50.f) * log1pf(ns);
        } else {
            noneg += 1.f;
        }
    }
    #pragma unroll
    for (int m = 16; m; m >>= 1) {
        loss  += __shfl_xor_sync(0xffffffffu, loss, m);
        noneg += __shfl_xor_sync(0xffffffffu, noneg, m);
    }
    int w = tid >> 5;
    if ((tid & 31) == 0) { shl[w] = loss; shp[w] = noneg; }
    __syncthreads();
    if (tid == 0) {
        float L = 0.f, P = 0.f;
        int nw = blockDim.x >> 5;
        for (int k = 0; k < nw; k++) { L += shl[k]; P += shp[k]; }
        out[0] = L / (float)n;
        out[1] = P / (float)n;
        out[2] = g_last[1] / fmaxf(g_last[0], 1.f);
        out[3] = g_last[3] / fmaxf(g_last[2], 1.f);
    }
}

// -----------------------------------------------------------------------------
extern "C" void kernel_launch(void* const* d_in, const int* in_sizes, int n_in,
                              void* d_out, int out_size) {
    const float* x = (const float*)d_in[0];
    const int*   t = (const int*)d_in[1];
    int n = in_sizes[1];
    int d = in_sizes[0] / n;
    float* out = (float*)d_out;

    int pos_smem = TJC * DMAX * (int)sizeof(float);   // 96 KB

    static bool attr_done = false;
    if (!attr_done) {
        cudaFuncSetAttribute(pos_pass2, cudaFuncAttributeMaxDynamicSharedMemorySize, pos_smem);
        cudaFuncSetAttribute(neg_pass_mma, cudaFuncAttributeMaxDynamicSharedMemorySize, NEG_SMEM);
        attr_done = true;
    }

    k_zero<<<1, 128>>>();
    k_hist<<<(n + 255) / 256, 256>>>(t, n);
    k_scan<<<1, 32>>>();
    k_scatter<<<(n + 255) / 256, 256>>>(t, n);
    k_split<<<(n * d + 255) / 256, 256>>>(x, n * d);

    pos_pass2<<<NCLS, 256, pos_smem>>>(x, n);

    dim3 grid2(8, n / BT);
    neg_pass_mma<<<grid2, 256, NEG_SMEM>>>(t, n);

    finalize<<<1, 256>>>(out, n);
}

// round 12
// speedup vs baseline: 1.9522x; 1.9522x over previous
#include <cuda_runtime.h>
#include <cuda_bf16.h>
#include <cstdint>
#include <stdint.h>
#include <math.h>

#define NMAX 8192
#define DMAX 128
#define NCLS 128

// Scratch (no cudaMalloc allowed)
__device__ float g_pos_min[NMAX];
__device__ float g_pos_sum[NMAX];
__device__ float g_neg_sum[NMAX];
__device__ float g_last[4];       // [0]=pos_cnt [1]=pos_simsum [2]=neg_cnt [3]=neg_simsum
__device__ int   g_cls_cnt[NCLS];
__device__ int   g_cls_off[NCLS + 1];
__device__ int   g_cls_cur[NCLS];
__device__ int   g_cls_list[NMAX];
__device__ __nv_bfloat16 g_xhi[NMAX * DMAX];
__device__ __nv_bfloat16 g_xlo[NMAX * DMAX];

// -----------------------------------------------------------------------------
// Setup kernels
// -----------------------------------------------------------------------------
__global__ void k_zero() {
    int i = threadIdx.x;
    if (i < NCLS) { g_cls_cnt[i] = 0; g_cls_cur[i] = 0; }
    if (i < 4) g_last[i] = 0.f;
}
__global__ void k_hist(const int* __restrict__ t, int n) {
    int i = blockIdx.x * blockDim.x + threadIdx.x;
    if (i < n) atomicAdd(&g_cls_cnt[t[i]], 1);
}
__global__ void k_scan() {
    if (threadIdx.x == 0) {
        int acc = 0;
        for (int c = 0; c < NCLS; c++) { g_cls_off[c] = acc; acc += g_cls_cnt[c]; }
        g_cls_off[NCLS] = acc;
    }
}
__global__ void k_scatter(const int* __restrict__ t, int n) {
    int i = blockIdx.x * blockDim.x + threadIdx.x;
    if (i < n) {
        int c = t[i];
        int p = atomicAdd(&g_cls_cur[c], 1);
        g_cls_list[g_cls_off[c] + p] = i;
    }
}
__global__ void k_split(const float* __restrict__ x, int n, int total) {
    int i = blockIdx.x * blockDim.x + threadIdx.x;
    if (i < total) {
        float v = x[i];
        __nv_bfloat16 hi = __float2bfloat16(v);
        g_xhi[i] = hi;
        g_xlo[i] = __float2bfloat16(v - __bfloat162float(hi));
        if (i < n) g_neg_sum[i] = 0.f;
    }
}

// -----------------------------------------------------------------------------
// Kernel 1: class-blocked positive pass (exact fp32).
// One CTA per class; member rows cached in smem; lane-per-j dense dots with
// staggered k (conflict-free LDS.128), 4 independent accumulators.
// -----------------------------------------------------------------------------
#define TJC 192

__global__ __launch_bounds__(256)
void pos_pass3(const float* __restrict__ x, int n, int d) {
    int cls = blockIdx.x;
    int beg = g_cls_off[cls], end = g_cls_off[cls + 1];
    int cnt = end - beg;
    if (cnt <= 0) return;

    extern __shared__ float4 sx[];        // TJC*32 float4 = 96 KB
    __shared__ int sidx[TJC];

    int tid = threadIdx.x, lane = tid & 31, wrp = tid >> 5;
    const float4* X4 = (const float4*)x;
    int d4 = d >> 2;                       // 32 for d=128
    bool fast = (cnt <= TJC) && (d4 == 32);

    if (fast) {
        for (int idx = tid; idx < cnt * 32; idx += 256) {
            int r = idx >> 5, c = idx & 31;
            sx[idx] = X4[(size_t)g_cls_list[beg + r] * 32 + c];
        }
        for (int m = tid; m < cnt; m += 256) sidx[m] = g_cls_list[beg + m];
    }
    __syncthreads();

    for (int mi = wrp; mi < cnt; mi += 8) {
        int i = fast ? sidx[mi] : g_cls_list[beg + mi];
        float pmin = INFINITY, psum = 0.f, pcnt = 0.f, psim = 0.f;

        for (int mj = lane; mj < cnt; mj += 32) {
            float s0 = 0.f, s1 = 0.f, s2 = 0.f, s3 = 0.f;
            if (fast) {
                const float4* xi = sx + mi * 32;
                const float4* xj = sx + mj * 32;
                #pragma unroll
                for (int kk = 0; kk < 32; kk += 4) {
                    int k0 = (kk + 0 + lane) & 31;
                    int k1 = (kk + 1 + lane) & 31;
                    int k2 = (kk + 2 + lane) & 31;
                    int k3 = (kk + 3 + lane) & 31;
                    float4 a0 = xi[k0], b0 = xj[k0];
                    float4 a1 = xi[k1], b1 = xj[k1];
                    float4 a2 = xi[k2], b2 = xj[k2];
                    float4 a3 = xi[k3], b3 = xj[k3];
                    s0 += a0.x * b0.x + a0.y * b0.y + a0.z * b0.z + a0.w * b0.w;
                    s1 += a1.x * b1.x + a1.y * b1.y + a1.z * b1.z + a1.w * b1.w;
                    s2 += a2.x * b2.x + a2.y * b2.y + a2.z * b2.z + a2.w * b2.w;
                    s3 += a3.x * b3.x + a3.y * b3.y + a3.z * b3.z + a3.w * b3.w;
                }
            } else {
                const float4* xi = X4 + (size_t)i * d4;
                const float4* xj = X4 + (size_t)g_cls_list[beg + mj] * d4;
                for (int k = 0; k < d4; k++) {
                    float4 a = xi[k], b = xj[k];
                    s0 += a.x * b.x + a.y * b.y + a.z * b.z + a.w * b.w;
                }
            }
            float s = (s0 + s1) + (s2 + s3);
            if (s < 0.9f) {                // diagonal (s = 1.0) excluded
                pmin = fminf(pmin, s);
                float dm = s - 0.9f;
                psum += expf(-2.f * (s - 0.5f) + dm * dm);
                pcnt += 1.f;
                psim += s;
            }
        }
        #pragma unroll
        for (int m = 16; m; m >>= 1) {
            pmin = fminf(pmin, __shfl_xor_sync(0xffffffffu, pmin, m));
            psum += __shfl_xor_sync(0xffffffffu, psum, m);
            pcnt += __shfl_xor_sync(0xffffffffu, pcnt, m);
            psim += __shfl_xor_sync(0xffffffffu, psim, m);
        }
        if (lane == 0) {
            g_pos_min[i] = pmin;
            g_pos_sum[i] = psum;
            if (i == n - 1) { g_last[0] = pcnt; g_last[1] = psim; }
        }
    }
}

// -----------------------------------------------------------------------------
// Kernel 2: 128x64-tile HMMA (bf16-split), occupancy 2, cp.async loads.
// Blocks with j0 >= i0 compute. "dual" (j0 >= i0+128): credit both directions.
// "straddle" (j0 in {i0, i0+64}): row-credit only — transpose pairs covered by
// the sibling straddle block; i==j auto-excluded by equal labels.
// sim = hi*hi + hi*lo + lo*hi (fp32 accum).
// -----------------------------------------------------------------------------
#define BM 128
#define BN 64
#define PAD 136                          // bf16 per padded smem row
#define ROWB (PAD * 2)                   // 272 B
#define A_TILE (BM * ROWB)               // 34816 B
#define B_TILE (BN * ROWB)               // 17408 B
#define NEG_SMEM (2 * A_TILE + 2 * B_TILE)   // 104448 B

__device__ __forceinline__ uint32_t smem_u32(const void* p) {
    uint32_t a;
    asm("{ .reg .u64 t; cvta.to.shared.u64 t, %1; cvt.u32.u64 %0, t; }"
        : "=r"(a) : "l"(p));
    return a;
}
__device__ __forceinline__ void cp_async16(uint32_t dst, const void* src) {
    asm volatile("cp.async.cg.shared.global [%0], [%1], 16;" :: "r"(dst), "l"(src));
}
__device__ __forceinline__ void mma16816(float* c, const unsigned* a, const unsigned* b) {
    asm volatile(
        "mma.sync.aligned.m16n8k16.row.col.f32.bf16.bf16.f32 "
        "{%0,%1,%2,%3}, {%4,%5,%6,%7}, {%8,%9}, {%0,%1,%2,%3};"
        : "+f"(c[0]), "+f"(c[1]), "+f"(c[2]), "+f"(c[3])
        : "r"(a[0]), "r"(a[1]), "r"(a[2]), "r"(a[3]), "r"(b[0]), "r"(b[1]));
}

__global__ __launch_bounds__(256, 2)
void neg_pass_mma(const int* __restrict__ t, int n) {
    int ib = blockIdx.y;                 // 128-row band
    int jt = blockIdx.x;                 // 64-col tile
    int i0 = ib * BM, j0 = jt * BN;
    if (j0 < i0) return;
    bool dual = (j0 >= i0 + BM);

    extern __shared__ char dsm[];
    uint32_t base = smem_u32(dsm);
    uint32_t Ahi = base, Alo = base + A_TILE;
    uint32_t Bhi = base + 2 * A_TILE, Blo = base + 2 * A_TILE + B_TILE;

    __shared__ float srow[BM], scol[BN], slast2[2];

    int tid  = threadIdx.x;
    int lane = tid & 31;
    int w    = tid >> 5;
    int wm   = w >> 1;                   // 0..3 -> 32-row strip
    int wn   = w & 1;                    // 0..1 -> 32-col strip
    int q    = lane >> 2;                // 0..7
    int tq   = lane & 3;                 // 0..3

    if (tid < BM) srow[tid] = 0.f;
    if (tid < BN) scol[tid] = 0.f;
    if (tid < 2)  slast2[tid] = 0.f;

    // async tile loads (row-linear padded layout)
    for (int idx = tid; idx < BM * 16; idx += 256) {
        int r = idx >> 4, ch = idx & 15;
        uint32_t off = (uint32_t)r * ROWB + (uint32_t)ch * 16u;
        cp_async16(Ahi + off, (const char*)(g_xhi + (size_t)(i0 + r) * DMAX) + ch * 16);
        cp_async16(Alo + off, (const char*)(g_xlo + (size_t)(i0 + r) * DMAX) + ch * 16);
    }
    for (int idx = tid; idx < BN * 16; idx += 256) {
        int r = idx >> 4, ch = idx & 15;
        uint32_t off = (uint32_t)r * ROWB + (uint32_t)ch * 16u;
        cp_async16(Bhi + off, (const char*)(g_xhi + (size_t)(j0 + r) * DMAX) + ch * 16);
        cp_async16(Blo + off, (const char*)(g_xlo + (size_t)(j0 + r) * DMAX) + ch * 16);
    }
    asm volatile("cp.async.commit_group;" ::: "memory");

    // labels/gates while loads fly
    int   tti[4]; float tpmR[4];         // ri = mf*2+rh, mf 0..1
    int   ttj[8]; float tpmC[8];         // ci = nf*2+cl, nf 0..3
    #pragma unroll
    for (int mf = 0; mf < 2; mf++)
        #pragma unroll
        for (int rh = 0; rh < 2; rh++) {
            int row = i0 + wm * 32 + mf * 16 + q + rh * 8;
            tti[mf * 2 + rh]  = t[row];
            tpmR[mf * 2 + rh] = g_pos_min[row];
        }
    #pragma unroll
    for (int nf = 0; nf < 4; nf++)
        #pragma unroll
        for (int cl = 0; cl < 2; cl++) {
            int col = j0 + wn * 32 + nf * 8 + tq * 2 + cl;
            ttj[nf * 2 + cl]  = t[col];
            tpmC[nf * 2 + cl] = g_pos_min[col];
        }

    asm volatile("cp.async.wait_group 0;" ::: "memory");
    __syncthreads();

    // ---- MMA: 3 bf16-split products ----
    float acc[2][4][4];
    #pragma unroll
    for (int mf = 0; mf < 2; mf++)
        #pragma unroll
        for (int nf = 0; nf < 4; nf++)
            #pragma unroll
            for (int r = 0; r < 4; r++) acc[mf][nf][r] = 0.f;

    const __nv_bfloat16* pAhi = (const __nv_bfloat16*)(dsm);
    const __nv_bfloat16* pAlo = (const __nv_bfloat16*)(dsm + A_TILE);
    const __nv_bfloat16* pBhi = (const __nv_bfloat16*)(dsm + 2 * A_TILE);
    const __nv_bfloat16* pBlo = (const __nv_bfloat16*)(dsm + 2 * A_TILE + B_TILE);

    #pragma unroll
    for (int kc = 0; kc < DMAX / 16; kc++) {
        int k0 = kc * 16;
        unsigned ah[2][4], al[2][4], bh[4][2], bl[4][2];
        #pragma unroll
        for (int mf = 0; mf < 2; mf++) {
            int r0 = wm * 32 + mf * 16 + q;
            const __nv_bfloat16* bse = pAhi + r0 * PAD + k0 + tq * 2;
            ah[mf][0] = *(const unsigned*)(bse);
            ah[mf][1] = *(const unsigned*)(bse + 8 * PAD);
            ah[mf][2] = *(const unsigned*)(bse + 8);
            ah[mf][3] = *(const unsigned*)(bse + 8 * PAD + 8);
            const __nv_bfloat16* bsl = pAlo + r0 * PAD + k0 + tq * 2;
            al[mf][0] = *(const unsigned*)(bsl);
            al[mf][1] = *(const unsigned*)(bsl + 8 * PAD);
            al[mf][2] = *(const unsigned*)(bsl + 8);
            al[mf][3] = *(const unsigned*)(bsl + 8 * PAD + 8);
        }
        #pragma unroll
        for (int nf = 0; nf < 4; nf++) {
            int c0 = wn * 32 + nf * 8 + q;
            const __nv_bfloat16* bse = pBhi + c0 * PAD + k0 + tq * 2;
            bh[nf][0] = *(const unsigned*)(bse);
            bh[nf][1] = *(const unsigned*)(bse + 8);
            const __nv_bfloat16* bsl = pBlo + c0 * PAD + k0 + tq * 2;
            bl[nf][0] = *(const unsigned*)(bsl);
            bl[nf][1] = *(const unsigned*)(bsl + 8);
        }
        #pragma unroll
        for (int mf = 0; mf < 2; mf++)
            #pragma unroll
            for (int nf = 0; nf < 4; nf++) {
                mma16816(acc[mf][nf], ah[mf], bh[nf]);   // hi*hi
                mma16816(acc[mf][nf], ah[mf], bl[nf]);   // hi*lo
                mma16816(acc[mf][nf], al[mf], bh[nf]);   // lo*hi
            }
    }

    // ---- epilogue ----
    bool iblast = (i0 + BM == n);
    bool jtlast = (j0 + BN == n);
    float rsum[4], csum[8];
    #pragma unroll
    for (int k = 0; k < 4; k++) rsum[k] = 0.f;
    #pragma unroll
    for (int k = 0; k < 8; k++) csum[k] = 0.f;

    #pragma unroll
    for (int mf = 0; mf < 2; mf++) {
        #pragma unroll
        for (int nf = 0; nf < 4; nf++) {
            #pragma unroll
            for (int r = 0; r < 4; r++) {
                float s = acc[mf][nf][r];
                int ri = mf * 2 + (r >> 1);
                int ci = nf * 2 + (r & 1);
                if (ttj[ci] != tti[ri] && s > 0.1f) {
                    float dm = 0.1f - s;
                    float e = __expf(50.f * (s - 0.5f) + dm * dm);
                    if (s + 0.5f > tpmR[ri]) {
                        rsum[ri] += e;
                        if (iblast) {
                            int row = i0 + wm * 32 + mf * 16 + q + (r >> 1) * 8;
                            if (row == n - 1) {
                                atomicAdd(&slast2[0], 1.f);
                                atomicAdd(&slast2[1], s);
                            }
                        }
                    }
                    if (dual && s + 0.5f > tpmC[ci]) {
                        csum[ci] += e;
                        if (jtlast) {
                            int col = j0 + wn * 32 + nf * 8 + tq * 2 + (r & 1);
                            if (col == n - 1) {
                                atomicAdd(&slast2[0], 1.f);
                                atomicAdd(&slast2[1], s);
                            }
                        }
                    }
                }
            }
        }
    }

    // row sums: reduce over tq (xor 1,2)
    #pragma unroll
    for (int ri = 0; ri < 4; ri++) {
        float v = rsum[ri];
        v += __shfl_xor_sync(0xffffffffu, v, 1);
        v += __shfl_xor_sync(0xffffffffu, v, 2);
        if (tq == 0 && v != 0.f) {
            int mf = ri >> 1, rh = ri & 1;
            atomicAdd(&srow[wm * 32 + mf * 16 + q + rh * 8], v);
        }
    }
    // col sums: reduce over q (xor 4,8,16)
    if (dual) {
        #pragma unroll
        for (int ci = 0; ci < 8; ci++) {
            float v = csum[ci];
            v += __shfl_xor_sync(0xffffffffu, v, 4);
            v += __shfl_xor_sync(0xffffffffu, v, 8);
            v += __shfl_xor_sync(0xffffffffu, v, 16);
            if (q == 0 && v != 0.f) {
                int nf = ci >> 1, cl = ci & 1;
                atomicAdd(&scol[wn * 32 + nf * 8 + tq * 2 + cl], v);
            }
        }
    }
    __syncthreads();

    if (tid < BM && srow[tid] != 0.f) atomicAdd(&g_neg_sum[i0 + tid], srow[tid]);
    if (dual && tid < BN && scol[tid] != 0.f) atomicAdd(&g_neg_sum[j0 + tid], scol[tid]);
    if (tid == 0 && slast2[0] != 0.f) {
        atomicAdd(&g_last[2], slast2[0]);
        atomicAdd(&g_last[3], slast2[1]);
    }
}

// -----------------------------------------------------------------------------
// Kernel 3: finalize
// -----------------------------------------------------------------------------
__global__ void finalize(float* __restrict__ out, int n) {
    __shared__ float shl[8], shp[8];
    int tid = threadIdx.x;
    float loss = 0.f, noneg = 0.f;
    for (int i = tid; i < n; i += blockDim.x) {
        float ns = g_neg_sum[i];
        if (ns > 0.f) {
            loss += 0.5f * log1pf(g_pos_sum[i]) + (1.f / 50.f) * log1pf(ns);
        } else {
            noneg += 1.f;
        }
    }
    #pragma unroll
    for (int m = 16; m; m >>= 1) {
        loss  += __shfl_xor_sync(0xffffffffu, loss, m);
        noneg += __shfl_xor_sync(0xffffffffu, noneg, m);
    }
    int w = tid >> 5;
    if ((tid & 31) == 0) { shl[w] = loss; shp[w] = noneg; }
    __syncthreads();
    if (tid == 0) {
        float L = 0.f, P = 0.f;
        int nw = blockDim.x >> 5;
        for (int k = 0; k < nw; k++) { L += shl[k]; P += shp[k]; }
        out[0] = L / (float)n;
        out[1] = P / (float)n;
        out[2] = g_last[1] / fmaxf(g_last[0], 1.f);
        out[3] = g_last[3] / fmaxf(g_last[2], 1.f);
    }
}

// -----------------------------------------------------------------------------
extern "C" void kernel_launch(void* const* d_in, const int* in_sizes, int n_in,
                              void* d_out, int out_size) {
    const float* x = (const float*)d_in[0];
    const int*   t = (const int*)d_in[1];
    int n = in_sizes[1];
    int d = in_sizes[0] / n;
    float* out = (float*)d_out;

    int pos_smem = TJC * DMAX * (int)sizeof(float);   // 96 KB

    static bool attr_done = false;
    if (!attr_done) {
        cudaFuncSetAttribute(pos_pass3, cudaFuncAttributeMaxDynamicSharedMemorySize, pos_smem);
        cudaFuncSetAttribute(neg_pass_mma, cudaFuncAttributeMaxDynamicSharedMemorySize, NEG_SMEM);
        attr_done = true;
    }

    k_zero<<<1, 128>>>();
    k_hist<<<(n + 255) / 256, 256>>>(t, n);
    k_scan<<<1, 32>>>();
    k_scatter<<<(n + 255) / 256, 256>>>(t, n);
    k_split<<<(n * d + 255) / 256, 256>>>(x, n, n * d);

    pos_pass3<<<NCLS, 256, pos_smem>>>(x, n, d);

    dim3 grid2(n / BN, n / BM);
    neg_pass_mma<<<grid2, 256, NEG_SMEM>>>(t, n);

    finalize<<<1, 256>>>(out, n);
}

// round 13
// speedup vs baseline: 2.0770x; 1.0640x over previous
#include <cuda_runtime.h>
#include <cuda_bf16.h>
#include <cstdint>
#include <stdint.h>
#include <math.h>

#define NMAX 8192
#define DMAX 128
#define NCLS 128

// Scratch (no cudaMalloc allowed)
__device__ float g_pos_min[NMAX];
__device__ float g_pos_sum[NMAX];
__device__ float g_neg_sum[NMAX];
__device__ float g_last[4];       // [0]=pos_cnt [1]=pos_simsum [2]=neg_cnt [3]=neg_simsum
__device__ int   g_cls_off[NCLS + 1];
__device__ int   g_cls_list[NMAX];
__device__ __nv_bfloat16 g_xhi[NMAX * DMAX];
__device__ __nv_bfloat16 g_xlo[NMAX * DMAX];

// -----------------------------------------------------------------------------
// Setup kernel 1: fused hist -> scan -> scatter (single CTA)
// -----------------------------------------------------------------------------
__global__ __launch_bounds__(1024)
void k_prep(const int* __restrict__ t, int n) {
    __shared__ int scnt[NCLS];
    __shared__ int scur[NCLS];
    int tid = threadIdx.x;
    if (tid < NCLS) scnt[tid] = 0;
    if (tid < 4) g_last[tid] = 0.f;
    __syncthreads();
    for (int i = tid; i < n; i += blockDim.x) atomicAdd(&scnt[t[i]], 1);
    __syncthreads();
    if (tid == 0) {
        int acc = 0;
        for (int c = 0; c < NCLS; c++) { g_cls_off[c] = acc; scur[c] = acc; acc += scnt[c]; }
        g_cls_off[NCLS] = acc;
    }
    __syncthreads();
    for (int i = tid; i < n; i += blockDim.x) {
        int p = atomicAdd(&scur[t[i]], 1);
        g_cls_list[p] = i;
    }
}

// Setup kernel 2: bf16 split + zero neg accumulators
__global__ void k_split(const float* __restrict__ x, int n, int total) {
    int i = blockIdx.x * blockDim.x + threadIdx.x;
    if (i < total) {
        float v = x[i];
        __nv_bfloat16 hi = __float2bfloat16(v);
        g_xhi[i] = hi;
        g_xlo[i] = __float2bfloat16(v - __bfloat162float(hi));
        if (i < n) g_neg_sum[i] = 0.f;
    }
}

// -----------------------------------------------------------------------------
// Kernel 1: class-blocked positive pass (exact fp32).
// -----------------------------------------------------------------------------
#define TJC 192

__global__ __launch_bounds__(256)
void pos_pass3(const float* __restrict__ x, int n, int d) {
    int cls = blockIdx.x;
    int beg = g_cls_off[cls], end = g_cls_off[cls + 1];
    int cnt = end - beg;
    if (cnt <= 0) return;

    extern __shared__ float4 sx[];        // TJC*32 float4 = 96 KB
    __shared__ int sidx[TJC];

    int tid = threadIdx.x, lane = tid & 31, wrp = tid >> 5;
    const float4* X4 = (const float4*)x;
    int d4 = d >> 2;
    bool fast = (cnt <= TJC) && (d4 == 32);

    if (fast) {
        for (int idx = tid; idx < cnt * 32; idx += 256) {
            int r = idx >> 5, c = idx & 31;
            sx[idx] = X4[(size_t)g_cls_list[beg + r] * 32 + c];
        }
        for (int m = tid; m < cnt; m += 256) sidx[m] = g_cls_list[beg + m];
    }
    __syncthreads();

    for (int mi = wrp; mi < cnt; mi += 8) {
        int i = fast ? sidx[mi] : g_cls_list[beg + mi];
        float pmin = INFINITY, psum = 0.f, pcnt = 0.f, psim = 0.f;

        for (int mj = lane; mj < cnt; mj += 32) {
            float s0 = 0.f, s1 = 0.f, s2 = 0.f, s3 = 0.f;
            if (fast) {
                const float4* xi = sx + mi * 32;
                const float4* xj = sx + mj * 32;
                #pragma unroll
                for (int kk = 0; kk < 32; kk += 4) {
                    int k0 = (kk + 0 + lane) & 31;
                    int k1 = (kk + 1 + lane) & 31;
                    int k2 = (kk + 2 + lane) & 31;
                    int k3 = (kk + 3 + lane) & 31;
                    float4 a0 = xi[k0], b0 = xj[k0];
                    float4 a1 = xi[k1], b1 = xj[k1];
                    float4 a2 = xi[k2], b2 = xj[k2];
                    float4 a3 = xi[k3], b3 = xj[k3];
                    s0 += a0.x * b0.x + a0.y * b0.y + a0.z * b0.z + a0.w * b0.w;
                    s1 += a1.x * b1.x + a1.y * b1.y + a1.z * b1.z + a1.w * b1.w;
                    s2 += a2.x * b2.x + a2.y * b2.y + a2.z * b2.z + a2.w * b2.w;
                    s3 += a3.x * b3.x + a3.y * b3.y + a3.z * b3.z + a3.w * b3.w;
                }
            } else {
                const float4* xi = X4 + (size_t)i * d4;
                const float4* xj = X4 + (size_t)g_cls_list[beg + mj] * d4;
                for (int k = 0; k < d4; k++) {
                    float4 a = xi[k], b = xj[k];
                    s0 += a.x * b.x + a.y * b.y + a.z * b.z + a.w * b.w;
                }
            }
            float s = (s0 + s1) + (s2 + s3);
            if (s < 0.9f) {                // diagonal (s = 1.0) excluded
                pmin = fminf(pmin, s);
                float dm = s - 0.9f;
                psum += expf(-2.f * (s - 0.5f) + dm * dm);
                pcnt += 1.f;
                psim += s;
            }
        }
        #pragma unroll
        for (int m = 16; m; m >>= 1) {
            pmin = fminf(pmin, __shfl_xor_sync(0xffffffffu, pmin, m));
            psum += __shfl_xor_sync(0xffffffffu, psum, m);
            pcnt += __shfl_xor_sync(0xffffffffu, pcnt, m);
            psim += __shfl_xor_sync(0xffffffffu, psim, m);
        }
        if (lane == 0) {
            g_pos_min[i] = pmin;
            g_pos_sum[i] = psum;
            if (i == n - 1) { g_last[0] = pcnt; g_last[1] = psim; }
        }
    }
}

// -----------------------------------------------------------------------------
// Kernel 2: 128x64-tile HMMA (bf16-split) with ldmatrix fragment loads.
// occ 2; dual/straddle symmetric crediting as before.
// -----------------------------------------------------------------------------
#define BM 128
#define BN 64
#define PAD 136                          // bf16 per padded smem row
#define ROWB (PAD * 2)                   // 272 B
#define A_TILE (BM * ROWB)               // 34816 B
#define B_TILE (BN * ROWB)               // 17408 B
#define NEG_SMEM (2 * A_TILE + 2 * B_TILE)   // 104448 B
#define FRAG16 (16 * ROWB)               // byte stride of 16 rows

__device__ __forceinline__ uint32_t smem_u32(const void* p) {
    uint32_t a;
    asm("{ .reg .u64 t; cvta.to.shared.u64 t, %1; cvt.u32.u64 %0, t; }"
        : "=r"(a) : "l"(p));
    return a;
}
__device__ __forceinline__ void cp_async16(uint32_t dst, const void* src) {
    asm volatile("cp.async.cg.shared.global [%0], [%1], 16;" :: "r"(dst), "l"(src));
}
__device__ __forceinline__ void ldsm4(unsigned* r, uint32_t addr) {
    asm volatile("ldmatrix.sync.aligned.m8n8.x4.shared.b16 {%0,%1,%2,%3}, [%4];"
                 : "=r"(r[0]), "=r"(r[1]), "=r"(r[2]), "=r"(r[3]) : "r"(addr));
}
__device__ __forceinline__ void mma16816(float* c, const unsigned* a, const unsigned* b) {
    asm volatile(
        "mma.sync.aligned.m16n8k16.row.col.f32.bf16.bf16.f32 "
        "{%0,%1,%2,%3}, {%4,%5,%6,%7}, {%8,%9}, {%0,%1,%2,%3};"
        : "+f"(c[0]), "+f"(c[1]), "+f"(c[2]), "+f"(c[3])
        : "r"(a[0]), "r"(a[1]), "r"(a[2]), "r"(a[3]), "r"(b[0]), "r"(b[1]));
}

__global__ __launch_bounds__(256, 2)
void neg_pass_mma(const int* __restrict__ t, int n) {
    int ib = blockIdx.y;                 // 128-row band
    int jt = blockIdx.x;                 // 64-col tile
    int i0 = ib * BM, j0 = jt * BN;
    if (j0 < i0) return;
    bool dual = (j0 >= i0 + BM);

    extern __shared__ char dsm[];
    uint32_t base = smem_u32(dsm);
    uint32_t Ahi = base, Alo = base + A_TILE;
    uint32_t Bhi = base + 2 * A_TILE, Blo = base + 2 * A_TILE + B_TILE;

    __shared__ float srow[BM], scol[BN], slast2[2];

    int tid  = threadIdx.x;
    int lane = tid & 31;
    int w    = tid >> 5;
    int wm   = w >> 1;                   // 0..3 -> 32-row strip
    int wn   = w & 1;                    // 0..1 -> 32-col strip
    int q    = lane >> 2;                // 0..7
    int tq   = lane & 3;                 // 0..3

    if (tid < BM) srow[tid] = 0.f;
    if (tid < BN) scol[tid] = 0.f;
    if (tid < 2)  slast2[tid] = 0.f;

    // async tile loads (row-linear padded layout)
    for (int idx = tid; idx < BM * 16; idx += 256) {
        int r = idx >> 4, ch = idx & 15;
        uint32_t off = (uint32_t)r * ROWB + (uint32_t)ch * 16u;
        cp_async16(Ahi + off, (const char*)(g_xhi + (size_t)(i0 + r) * DMAX) + ch * 16);
        cp_async16(Alo + off, (const char*)(g_xlo + (size_t)(i0 + r) * DMAX) + ch * 16);
    }
    for (int idx = tid; idx < BN * 16; idx += 256) {
        int r = idx >> 4, ch = idx & 15;
        uint32_t off = (uint32_t)r * ROWB + (uint32_t)ch * 16u;
        cp_async16(Bhi + off, (const char*)(g_xhi + (size_t)(j0 + r) * DMAX) + ch * 16);
        cp_async16(Blo + off, (const char*)(g_xlo + (size_t)(j0 + r) * DMAX) + ch * 16);
    }
    asm volatile("cp.async.commit_group;" ::: "memory");

    // labels/gates while loads fly
    int   tti[4]; float tpmR[4];
    int   ttj[8]; float tpmC[8];
    #pragma unroll
    for (int mf = 0; mf < 2; mf++)
        #pragma unroll
        for (int rh = 0; rh < 2; rh++) {
            int row = i0 + wm * 32 + mf * 16 + q + rh * 8;
            tti[mf * 2 + rh]  = t[row];
            tpmR[mf * 2 + rh] = g_pos_min[row];
        }
    #pragma unroll
    for (int nf = 0; nf < 4; nf++)
        #pragma unroll
        for (int cl = 0; cl < 2; cl++) {
            int col = j0 + wn * 32 + nf * 8 + tq * 2 + cl;
            ttj[nf * 2 + cl]  = t[col];
            tpmC[nf * 2 + cl] = g_pos_min[col];
        }

    // ldmatrix lane-address bases (bytes)
    // A: x4 covers 16x16: rows r0 + (lane&15), col halves via lane>>4
    uint32_t aoff = (uint32_t)(wm * 32 + (lane & 15)) * ROWB
                  + ((lane >> 4) & 1) * 16u;
    // B: x4 covers two nf (16 N-rows) x 16 k: rows c0 + (lane&7) + ((lane>>4)&1)*8,
    //    col halves via (lane>>3)&1
    uint32_t boff = (uint32_t)(wn * 32 + (lane & 7) + ((lane >> 4) & 1) * 8) * ROWB
                  + ((lane >> 3) & 1) * 16u;

    asm volatile("cp.async.wait_group 0;" ::: "memory");
    __syncthreads();

    // ---- MMA: 3 bf16-split products ----
    float acc[2][4][4];
    #pragma unroll
    for (int mf = 0; mf < 2; mf++)
        #pragma unroll
        for (int nf = 0; nf < 4; nf++)
            #pragma unroll
            for (int r = 0; r < 4; r++) acc[mf][nf][r] = 0.f;

    #pragma unroll
    for (int kc = 0; kc < DMAX / 16; kc++) {
        uint32_t kb = (uint32_t)kc * 32u;
        unsigned ah[2][4], al[2][4], bh[4][2], bl[4][2];
        ldsm4(ah[0], Ahi + aoff + kb);
        ldsm4(ah[1], Ahi + aoff + FRAG16 + kb);
        ldsm4(al[0], Alo + aoff + kb);
        ldsm4(al[1], Alo + aoff + FRAG16 + kb);
        ldsm4(&bh[0][0], Bhi + boff + kb);            // b[0][0..1], b[1][0..1]
        ldsm4(&bh[2][0], Bhi + boff + FRAG16 + kb);   // b[2][0..1], b[3][0..1]
        ldsm4(&bl[0][0], Blo + boff + kb);
        ldsm4(&bl[2][0], Blo + boff + FRAG16 + kb);
        #pragma unroll
        for (int mf = 0; mf < 2; mf++)
            #pragma unroll
            for (int nf = 0; nf < 4; nf++) {
                mma16816(acc[mf][nf], ah[mf], bh[nf]);   // hi*hi
                mma16816(acc[mf][nf], ah[mf], bl[nf]);   // hi*lo
                mma16816(acc[mf][nf], al[mf], bh[nf]);   // lo*hi
            }
    }

    // ---- epilogue ----
    bool iblast = (i0 + BM == n);
    bool jtlast = (j0 + BN == n);
    float rsum[4], csum[8];
    #pragma unroll
    for (int k = 0; k < 4; k++) rsum[k] = 0.f;
    #pragma unroll
    for (int k = 0; k < 8; k++) csum[k] = 0.f;

    #pragma unroll
    for (int mf = 0; mf < 2; mf++) {
        #pragma unroll
        for (int nf = 0; nf < 4; nf++) {
            #pragma unroll
            for (int r = 0; r < 4; r++) {
                float s = acc[mf][nf][r];
                int ri = mf * 2 + (r >> 1);
                int ci = nf * 2 + (r & 1);
                if (ttj[ci] != tti[ri] && s > 0.1f) {
                    float dm = 0.1f - s;
                    float e = __expf(50.f * (s - 0.5f) + dm * dm);
                    if (s + 0.5f > tpmR[ri]) {
                        rsum[ri] += e;
                        if (iblast) {
                            int row = i0 + wm * 32 + mf * 16 + q + (r >> 1) * 8;
                            if (row == n - 1) {
                                atomicAdd(&slast2[0], 1.f);
                                atomicAdd(&slast2[1], s);
                            }
                        }
                    }
                    if (dual && s + 0.5f > tpmC[ci]) {
                        csum[ci] += e;
                        if (jtlast) {
                            int col = j0 + wn * 32 + nf * 8 + tq * 2 + (r & 1);
                            if (col == n - 1) {
                                atomicAdd(&slast2[0], 1.f);
                                atomicAdd(&slast2[1], s);
                            }
                        }
                    }
                }
            }
        }
    }

    // row sums: reduce over tq (xor 1,2)
    #pragma unroll
    for (int ri = 0; ri < 4; ri++) {
        float v = rsum[ri];
        v += __shfl_xor_sync(0xffffffffu, v, 1);
        v += __shfl_xor_sync(0xffffffffu, v, 2);
        if (tq == 0 && v != 0.f) {
            int mf = ri >> 1, rh = ri & 1;
            atomicAdd(&srow[wm * 32 + mf * 16 + q + rh * 8], v);
        }
    }
    // col sums: reduce over q (xor 4,8,16)
    if (dual) {
        #pragma unroll
        for (int ci = 0; ci < 8; ci++) {
            float v = csum[ci];
            v += __shfl_xor_sync(0xffffffffu, v, 4);
            v += __shfl_xor_sync(0xffffffffu, v, 8);
            v += __shfl_xor_sync(0xffffffffu, v, 16);
            if (q == 0 && v != 0.f) {
                int nf = ci >> 1, cl = ci & 1;
                atomicAdd(&scol[wn * 32 + nf * 8 + tq * 2 + cl], v);
            }
        }
    }
    __syncthreads();

    if (tid < BM && srow[tid] != 0.f) atomicAdd(&g_neg_sum[i0 + tid], srow[tid]);
    if (dual && tid < BN && scol[tid] != 0.f) atomicAdd(&g_neg_sum[j0 + tid], scol[tid]);
    if (tid == 0 && slast2[0] != 0.f) {
        atomicAdd(&g_last[2], slast2[0]);
        atomicAdd(&g_last[3], slast2[1]);
    }
}

// -----------------------------------------------------------------------------
// Kernel 3: finalize
// -----------------------------------------------------------------------------
__global__ void finalize(float* __restrict__ out, int n) {
    __shared__ float shl[8], shp[8];
    int tid = threadIdx.x;
    float loss = 0.f, noneg = 0.f;
    for (int i = tid; i < n; i += blockDim.x) {
        float ns = g_neg_sum[i];
        if (ns > 0.f) {
            loss += 0.5f * log1pf(g_pos_sum[i]) + (1.f / 50.f) * log1pf(ns);
        } else {
            noneg += 1.f;
        }
    }
    #pragma unroll
    for (int m = 16; m; m >>= 1) {
        loss  += __shfl_xor_sync(0xffffffffu, loss, m);
        noneg += __shfl_xor_sync(0xffffffffu, noneg, m);
    }
    int w = tid >> 5;
    if ((tid & 31) == 0) { shl[w] = loss; shp[w] = noneg; }
    __syncthreads();
    if (tid == 0) {
        float L = 0.f, P = 0.f;
        int nw = blockDim.x >> 5;
        for (int k = 0; k < nw; k++) { L += shl[k]; P += shp[k]; }
        out[0] = L / (float)n;
        out[1] = P / (float)n;
        out[2] = g_last[1] / fmaxf(g_last[0], 1.f);
        out[3] = g_last[3] / fmaxf(g_last[2], 1.f);
    }
}

// -----------------------------------------------------------------------------
extern "C" void kernel_launch(void* const* d_in, const int* in_sizes, int n_in,
                              void* d_out, int out_size) {
    const float* x = (const float*)d_in[0];
    const int*   t = (const int*)d_in[1];
    int n = in_sizes[1];
    int d = in_sizes[0] / n;
    float* out = (float*)d_out;

    int pos_smem = TJC * DMAX * (int)sizeof(float);   // 96 KB

    static bool attr_done = false;
    if (!attr_done) {
        cudaFuncSetAttribute(pos_pass3, cudaFuncAttributeMaxDynamicSharedMemorySize, pos_smem);
        cudaFuncSetAttribute(neg_pass_mma, cudaFuncAttributeMaxDynamicSharedMemorySize, NEG_SMEM);
        attr_done = true;
    }

    k_prep<<<1, 1024>>>(t, n);
    k_split<<<(n * d + 255) / 256, 256>>>(x, n, n * d);

    pos_pass3<<<NCLS, 256, pos_smem>>>(x, n, d);

    dim3 grid2(n / BN, n / BM);
    neg_pass_mma<<<grid2, 256, NEG_SMEM>>>(t, n);

    finalize<<<1, 256>>>(out, n);
}

// round 14
// speedup vs baseline: 2.4312x; 1.1705x over previous
#include <cuda_runtime.h>
#include <cuda_bf16.h>
#include <cstdint>
#include <stdint.h>
#include <math.h>

#define NMAX 8192
#define DMAX 128
#define NCLS 128

// Scratch (no cudaMalloc allowed)
__device__ float g_pos_min[NMAX];
__device__ float g_pos_sum[NMAX];
__device__ float g_neg_sum[NMAX];
__device__ float g_last[4];       // [0]=pos_cnt [1]=pos_simsum [2]=neg_cnt [3]=neg_simsum
__device__ int   g_cls_off[NCLS + 1];
__device__ int   g_cls_list[NMAX];
__device__ __nv_bfloat16 g_xhi[NMAX * DMAX];
__device__ __nv_bfloat16 g_xlo[NMAX * DMAX];

// -----------------------------------------------------------------------------
// Setup kernel 1: fused hist -> scan -> scatter (single CTA)
// -----------------------------------------------------------------------------
__global__ __launch_bounds__(1024)
void k_prep(const int* __restrict__ t, int n) {
    __shared__ int scnt[NCLS];
    __shared__ int scur[NCLS];
    int tid = threadIdx.x;
    if (tid < NCLS) scnt[tid] = 0;
    if (tid < 4) g_last[tid] = 0.f;
    __syncthreads();
    for (int i = tid; i < n; i += blockDim.x) atomicAdd(&scnt[t[i]], 1);
    __syncthreads();
    if (tid == 0) {
        int acc = 0;
        for (int c = 0; c < NCLS; c++) { g_cls_off[c] = acc; scur[c] = acc; acc += scnt[c]; }
        g_cls_off[NCLS] = acc;
    }
    __syncthreads();
    for (int i = tid; i < n; i += blockDim.x) {
        int p = atomicAdd(&scur[t[i]], 1);
        g_cls_list[p] = i;
    }
}

// Setup kernel 2: bf16 split + zero neg accumulators
__global__ void k_split(const float* __restrict__ x, int n, int total) {
    int i = blockIdx.x * blockDim.x + threadIdx.x;
    if (i < total) {
        float v = x[i];
        __nv_bfloat16 hi = __float2bfloat16(v);
        g_xhi[i] = hi;
        g_xlo[i] = __float2bfloat16(v - __bfloat162float(hi));
        if (i < n) g_neg_sum[i] = 0.f;
    }
}

// -----------------------------------------------------------------------------
// ordered-uint float key helpers (for atomicMin on floats incl. negatives)
// -----------------------------------------------------------------------------
__device__ __forceinline__ unsigned fkey(float f) {
    unsigned u = __float_as_uint(f);
    return (u & 0x80000000u) ? ~u : (u | 0x80000000u);
}
__device__ __forceinline__ float fdec(unsigned k) {
    return (k & 0x80000000u) ? __uint_as_float(k ^ 0x80000000u)
                             : __uint_as_float(~k);
}

// -----------------------------------------------------------------------------
// Kernel 1: class-blocked positive pass (exact fp32), micro-tiled Gram.
// One CTA per class. Warps compute 16x16 dot tiles over the class Gram
// matrix (triangular enumeration; off-diagonal tiles credit both rows and
// cols). Lane = 2 rows x 4 cols. Shared-atomic per-row accumulators.
// -----------------------------------------------------------------------------
#define TJC  192
#define PPAD 33     // float4 stride per row -> bank-staggered (4*r mod 32)

__global__ __launch_bounds__(256)
void pos_pass4(const float* __restrict__ x, int n, int d) {
    int cls = blockIdx.x;
    int beg = g_cls_off[cls], end = g_cls_off[cls + 1];
    int cnt = end - beg;
    if (cnt <= 0) return;

    extern __shared__ float4 sx[];        // TJC*PPAD float4 = 99 KB
    __shared__ int      sidx[TJC];
    __shared__ unsigned skey[TJC];
    __shared__ float    spsum[TJC], spcnt[TJC], spsim[TJC];

    int tid = threadIdx.x, lane = tid & 31, wrp = tid >> 5;
    const float4* X4 = (const float4*)x;
    int d4 = d >> 2;

    if (cnt <= TJC && d4 == 32) {
        for (int m = tid; m < cnt; m += 256) {
            sidx[m] = g_cls_list[beg + m];
            skey[m] = 0xFF800000u;        // fkey(+inf)
            spsum[m] = 0.f; spcnt[m] = 0.f; spsim[m] = 0.f;
        }
        for (int idx = tid; idx < cnt * 32; idx += 256) {
            int r = idx >> 5, c = idx & 31;
            sx[r * PPAD + c] = X4[(size_t)g_cls_list[beg + r] * 32 + c];
        }
        __syncthreads();

        int nt = (cnt + 15) >> 4;
        int ntri = (nt * (nt + 1)) >> 1;
        int r8 = lane & 7, c8 = lane >> 3;

        for (int tt = wrp; tt < ntri; tt += 8) {
            int ti = 0, rem = tt;
            while (rem >= nt - ti) { rem -= nt - ti; ti++; }
            int tj = ti + rem;
            bool offd = (ti < tj);

            int ri0 = ti * 16 + r8;
            int ri1 = ri0 + 8;
            int cjb = tj * 16 + c8 * 4;

            const float4* a0p = sx + min(ri0, cnt - 1) * PPAD;
            const float4* a1p = sx + min(ri1, cnt - 1) * PPAD;
            const float4* b0p = sx + min(cjb + 0, cnt - 1) * PPAD;
            const float4* b1p = sx + min(cjb + 1, cnt - 1) * PPAD;
            const float4* b2p = sx + min(cjb + 2, cnt - 1) * PPAD;
            const float4* b3p = sx + min(cjb + 3, cnt - 1) * PPAD;

            float acc[2][4];
            #pragma unroll
            for (int a = 0; a < 2; a++)
                #pragma unroll
                for (int b = 0; b < 4; b++) acc[a][b] = 0.f;

            #pragma unroll 8
            for (int k = 0; k < 32; k++) {
                float4 a0 = a0p[k], a1 = a1p[k];
                float4 b0 = b0p[k], b1 = b1p[k], b2 = b2p[k], b3 = b3p[k];
                acc[0][0] += a0.x*b0.x + a0.y*b0.y + a0.z*b0.z + a0.w*b0.w;
                acc[0][1] += a0.x*b1.x + a0.y*b1.y + a0.z*b1.z + a0.w*b1.w;
                acc[0][2] += a0.x*b2.x + a0.y*b2.y + a0.z*b2.z + a0.w*b2.w;
                acc[0][3] += a0.x*b3.x + a0.y*b3.y + a0.z*b3.z + a0.w*b3.w;
                acc[1][0] += a1.x*b0.x + a1.y*b0.y + a1.z*b0.z + a1.w*b0.w;
                acc[1][1] += a1.x*b1.x + a1.y*b1.y + a1.z*b1.z + a1.w*b1.w;
                acc[1][2] += a1.x*b2.x + a1.y*b2.y + a1.z*b2.z + a1.w*b2.w;
                acc[1][3] += a1.x*b3.x + a1.y*b3.y + a1.z*b3.z + a1.w*b3.w;
            }

            // per-cell contributions
            float rowE[2] = {0.f, 0.f}, rowC[2] = {0.f, 0.f}, rowS[2] = {0.f, 0.f};
            unsigned rowK[2] = {0xFF800000u, 0xFF800000u};
            float colE[4] = {0.f,0.f,0.f,0.f}, colC[4] = {0.f,0.f,0.f,0.f}, colS[4] = {0.f,0.f,0.f,0.f};
            unsigned colK[4] = {0xFF800000u,0xFF800000u,0xFF800000u,0xFF800000u};

            #pragma unroll
            for (int rr = 0; rr < 2; rr++) {
                int ri = rr ? ri1 : ri0;
                bool vr = (ri < cnt);
                #pragma unroll
                for (int jj = 0; jj < 4; jj++) {
                    float s = acc[rr][jj];
                    if (vr && (cjb + jj) < cnt && s < 0.9f) {   // diag s=1 excluded
                        float dm = s - 0.9f;
                        float e = expf(-2.f * (s - 0.5f) + dm * dm);
                        unsigned kk = fkey(s);
                        rowE[rr] += e; rowC[rr] += 1.f; rowS[rr] += s;
                        rowK[rr] = min(rowK[rr], kk);
                        if (offd) {
                            colE[jj] += e; colC[jj] += 1.f; colS[jj] += s;
                            colK[jj] = min(colK[jj], kk);
                        }
                    }
                }
            }

            // row reduce over c8 (xor 8,16), atomics from c8==0
            #pragma unroll
            for (int rr = 0; rr < 2; rr++) {
                rowE[rr] += __shfl_xor_sync(0xffffffffu, rowE[rr], 8);
                rowC[rr] += __shfl_xor_sync(0xffffffffu, rowC[rr], 8);
                rowS[rr] += __shfl_xor_sync(0xffffffffu, rowS[rr], 8);
                rowK[rr] = min(rowK[rr], __shfl_xor_sync(0xffffffffu, rowK[rr], 8));
                rowE[rr] += __shfl_xor_sync(0xffffffffu, rowE[rr], 16);
                rowC[rr] += __shfl_xor_sync(0xffffffffu, rowC[rr], 16);
                rowS[rr] += __shfl_xor_sync(0xffffffffu, rowS[rr], 16);
                rowK[rr] = min(rowK[rr], __shfl_xor_sync(0xffffffffu, rowK[rr], 16));
                int ri = rr ? ri1 : ri0;
                if (c8 == 0 && ri < cnt && rowC[rr] > 0.f) {
                    atomicAdd(&spsum[ri], rowE[rr]);
                    atomicAdd(&spcnt[ri], rowC[rr]);
                    atomicAdd(&spsim[ri], rowS[rr]);
                    atomicMin(&skey[ri], rowK[rr]);
                }
            }
            // col reduce over r8 (xor 1,2,4), atomics from r8==0
            if (offd) {
                #pragma unroll
                for (int jj = 0; jj < 4; jj++) {
                    colE[jj] += __shfl_xor_sync(0xffffffffu, colE[jj], 1);
                    colC[jj] += __shfl_xor_sync(0xffffffffu, colC[jj], 1);
                    colS[jj] += __shfl_xor_sync(0xffffffffu, colS[jj], 1);
                    colK[jj] = min(colK[jj], __shfl_xor_sync(0xffffffffu, colK[jj], 1));
                    colE[jj] += __shfl_xor_sync(0xffffffffu, colE[jj], 2);
                    colC[jj] += __shfl_xor_sync(0xffffffffu, colC[jj], 2);
                    colS[jj] += __shfl_xor_sync(0xffffffffu, colS[jj], 2);
                    colK[jj] = min(colK[jj], __shfl_xor_sync(0xffffffffu, colK[jj], 2));
                    colE[jj] += __shfl_xor_sync(0xffffffffu, colE[jj], 4);
                    colC[jj] += __shfl_xor_sync(0xffffffffu, colC[jj], 4);
                    colS[jj] += __shfl_xor_sync(0xffffffffu, colS[jj], 4);
                    colK[jj] = min(colK[jj], __shfl_xor_sync(0xffffffffu, colK[jj], 4));
                    int cj = cjb + jj;
                    if (r8 == 0 && cj < cnt && colC[jj] > 0.f) {
                        atomicAdd(&spsum[cj], colE[jj]);
                        atomicAdd(&spcnt[cj], colC[jj]);
                        atomicAdd(&spsim[cj], colS[jj]);
                        atomicMin(&skey[cj], colK[jj]);
                    }
                }
            }
        }
        __syncthreads();

        for (int m = tid; m < cnt; m += 256) {
            int i = sidx[m];
            g_pos_min[i] = fdec(skey[m]);
            g_pos_sum[i] = spsum[m];
            if (i == n - 1) { g_last[0] = spcnt[m]; g_last[1] = spsim[m]; }
        }
    } else {
        // fallback (not expected for this dataset): warp-per-i from global
        for (int mi = wrp; mi < cnt; mi += 8) {
            int i = g_cls_list[beg + mi];
            float pmin = INFINITY, psum = 0.f, pcnt = 0.f, psim = 0.f;
            for (int mj = lane; mj < cnt; mj += 32) {
                const float4* xi = X4 + (size_t)i * d4;
                const float4* xj = X4 + (size_t)g_cls_list[beg + mj] * d4;
                float s = 0.f;
                for (int k = 0; k < d4; k++) {
                    float4 a = xi[k], b = xj[k];
                    s += a.x*b.x + a.y*b.y + a.z*b.z + a.w*b.w;
                }
                if (s < 0.9f) {
                    pmin = fminf(pmin, s);
                    float dm = s - 0.9f;
                    psum += expf(-2.f * (s - 0.5f) + dm * dm);
                    pcnt += 1.f;
                    psim += s;
                }
            }
            #pragma unroll
            for (int m = 16; m; m >>= 1) {
                pmin = fminf(pmin, __shfl_xor_sync(0xffffffffu, pmin, m));
                psum += __shfl_xor_sync(0xffffffffu, psum, m);
                pcnt += __shfl_xor_sync(0xffffffffu, pcnt, m);
                psim += __shfl_xor_sync(0xffffffffu, psim, m);
            }
            if (lane == 0) {
                g_pos_min[i] = pmin;
                g_pos_sum[i] = psum;
                if (i == n - 1) { g_last[0] = pcnt; g_last[1] = psim; }
            }
        }
    }
}

// -----------------------------------------------------------------------------
// Kernel 2: 64x64-tile HMMA (bf16-split), ldmatrix loads, occupancy 3.
// Square tiles: diagonal (j0==i0) row-credit only (transpose cells in-tile);
// off-diagonal (j0>i0) dual credit. sim = hi*hi + hi*lo + lo*hi (fp32).
// -----------------------------------------------------------------------------
#define NBT   64
#define NROWB 272                       // padded row bytes (136 bf16)
#define NTILE (NBT * NROWB)             // 17408 B
#define NEG_SMEM (4 * NTILE)            // 69632 B
#define NFRAG16 (16 * NROWB)

__device__ __forceinline__ uint32_t smem_u32(const void* p) {
    uint32_t a;
    asm("{ .reg .u64 t; cvta.to.shared.u64 t, %1; cvt.u32.u64 %0, t; }"
        : "=r"(a) : "l"(p));
    return a;
}
__device__ __forceinline__ void cp_async16(uint32_t dst, const void* src) {
    asm volatile("cp.async.cg.shared.global [%0], [%1], 16;" :: "r"(dst), "l"(src));
}
__device__ __forceinline__ void ldsm4(unsigned* r, uint32_t addr) {
    asm volatile("ldmatrix.sync.aligned.m8n8.x4.shared.b16 {%0,%1,%2,%3}, [%4];"
                 : "=r"(r[0]), "=r"(r[1]), "=r"(r[2]), "=r"(r[3]) : "r"(addr));
}
__device__ __forceinline__ void mma16816(float* c, const unsigned* a, const unsigned* b) {
    asm volatile(
        "mma.sync.aligned.m16n8k16.row.col.f32.bf16.bf16.f32 "
        "{%0,%1,%2,%3}, {%4,%5,%6,%7}, {%8,%9}, {%0,%1,%2,%3};"
        : "+f"(c[0]), "+f"(c[1]), "+f"(c[2]), "+f"(c[3])
        : "r"(a[0]), "r"(a[1]), "r"(a[2]), "r"(a[3]), "r"(b[0]), "r"(b[1]));
}

__global__ __launch_bounds__(256, 3)
void neg_pass_mma(const int* __restrict__ t, int n) {
    int ib = blockIdx.y, jt = blockIdx.x;
    int i0 = ib * NBT, j0 = jt * NBT;
    if (j0 < i0) return;
    bool dual = (j0 > i0);

    extern __shared__ char dsm[];
    uint32_t base = smem_u32(dsm);
    uint32_t Ahi = base, Alo = base + NTILE;
    uint32_t Bhi = base + 2 * NTILE, Blo = base + 3 * NTILE;

    __shared__ float srow[NBT], scol[NBT], slast2[2];
    __shared__ int   sRowT[NBT], sColT[NBT];
    __shared__ float sRowP[NBT], sColP[NBT];

    int tid  = threadIdx.x;
    int lane = tid & 31;
    int w    = tid >> 5;
    int wm   = w >> 2;                   // 0..1 -> 32-row strip
    int wn   = w & 3;                    // 0..3 -> 16-col strip
    int q    = lane >> 2;                // 0..7
    int tq   = lane & 3;                 // 0..3

    // async tile loads (row-linear padded layout)
    for (int idx = tid; idx < NBT * 16; idx += 256) {
        int r = idx >> 4, ch = idx & 15;
        uint32_t off = (uint32_t)r * NROWB + (uint32_t)ch * 16u;
        cp_async16(Ahi + off, (const char*)(g_xhi + (size_t)(i0 + r) * DMAX) + ch * 16);
        cp_async16(Alo + off, (const char*)(g_xlo + (size_t)(i0 + r) * DMAX) + ch * 16);
        cp_async16(Bhi + off, (const char*)(g_xhi + (size_t)(j0 + r) * DMAX) + ch * 16);
        cp_async16(Blo + off, (const char*)(g_xlo + (size_t)(j0 + r) * DMAX) + ch * 16);
    }
    asm volatile("cp.async.commit_group;" ::: "memory");

    // labels/gates to shared while loads fly
    if (tid < NBT) {
        srow[tid] = 0.f; scol[tid] = 0.f;
        sRowT[tid] = t[i0 + tid];          sColT[tid] = t[j0 + tid];
        sRowP[tid] = g_pos_min[i0 + tid];  sColP[tid] = g_pos_min[j0 + tid];
    }
    if (tid < 2) slast2[tid] = 0.f;

    uint32_t aoff = (uint32_t)(wm * 32 + (lane & 15)) * NROWB + ((lane >> 4) & 1) * 16u;
    uint32_t boff = (uint32_t)(wn * 16 + (lane & 7) + ((lane >> 4) & 1) * 8) * NROWB
                  + ((lane >> 3) & 1) * 16u;

    asm volatile("cp.async.wait_group 0;" ::: "memory");
    __syncthreads();

    // ---- MMA: 3 bf16-split products ----
    float acc[2][2][4];
    #pragma unroll
    for (int mf = 0; mf < 2; mf++)
        #pragma unroll
        for (int nf = 0; nf < 2; nf++)
            #pragma unroll
            for (int r = 0; r < 4; r++) acc[mf][nf][r] = 0.f;

    #pragma unroll
    for (int kc = 0; kc < DMAX / 16; kc++) {
        uint32_t kb = (uint32_t)kc * 32u;
        unsigned ah[2][4], al[2][4], bh[4], bl[4];
        ldsm4(ah[0], Ahi + aoff + kb);
        ldsm4(ah[1], Ahi + aoff + NFRAG16 + kb);
        ldsm4(al[0], Alo + aoff + kb);
        ldsm4(al[1], Alo + aoff + NFRAG16 + kb);
        ldsm4(bh, Bhi + boff + kb);          // nf0{k0,k1}, nf1{k0,k1}
        ldsm4(bl, Blo + boff + kb);
        #pragma unroll
        for (int mf = 0; mf < 2; mf++)
            #pragma unroll
            for (int nf = 0; nf < 2; nf++) {
                mma16816(acc[mf][nf], ah[mf], bh + nf * 2);   // hi*hi
                mma16816(acc[mf][nf], ah[mf], bl + nf * 2);   // hi*lo
                mma16816(acc[mf][nf], al[mf], bh + nf * 2);   // lo*hi
            }
    }

    // ---- epilogue ----
    bool iblast = (i0 + NBT == n);
    bool jtlast = (j0 + NBT == n);
    float rsum[4], csum[4];
    #pragma unroll
    for (int k = 0; k < 4; k++) { rsum[k] = 0.f; csum[k] = 0.f; }

    #pragma unroll
    for (int mf = 0; mf < 2; mf++) {
        #pragma unroll
        for (int nf = 0; nf < 2; nf++) {
            #pragma unroll
            for (int r = 0; r < 4; r++) {
                float s = acc[mf][nf][r];
                int ri = mf * 2 + (r >> 1);
                int ci = nf * 2 + (r & 1);
                int row_l = wm * 32 + mf * 16 + q + (r >> 1) * 8;
                int col_l = wn * 16 + nf * 8 + tq * 2 + (r & 1);
                if (sColT[col_l] != sRowT[row_l] && s > 0.1f) {
                    float dm = 0.1f - s;
                    float e = __expf(50.f * (s - 0.5f) + dm * dm);
                    if (s + 0.5f > sRowP[row_l]) {
                        rsum[ri] += e;
                        if (iblast && i0 + row_l == n - 1) {
                            atomicAdd(&slast2[0], 1.f);
                            atomicAdd(&slast2[1], s);
                        }
                    }
                    if (dual && s + 0.5f > sColP[col_l]) {
                        csum[ci] += e;
                        if (jtlast && j0 + col_l == n - 1) {
                            atomicAdd(&slast2[0], 1.f);
                            atomicAdd(&slast2[1], s);
                        }
                    }
                }
            }
        }
    }

    // row sums: reduce over tq (xor 1,2)
    #pragma unroll
    for (int ri = 0; ri < 4; ri++) {
        float v = rsum[ri];
        v += __shfl_xor_sync(0xffffffffu, v, 1);
        v += __shfl_xor_sync(0xffffffffu, v, 2);
        if (tq == 0 && v != 0.f) {
            int mf = ri >> 1, rh = ri & 1;
            atomicAdd(&srow[wm * 32 + mf * 16 + q + rh * 8], v);
        }
    }
    // col sums: reduce over q (xor 4,8,16)
    if (dual) {
        #pragma unroll
        for (int ci = 0; ci < 4; ci++) {
            float v = csum[ci];
            v += __shfl_xor_sync(0xffffffffu, v, 4);
            v += __shfl_xor_sync(0xffffffffu, v, 8);
            v += __shfl_xor_sync(0xffffffffu, v, 16);
            if (q == 0 && v != 0.f) {
                int nf = ci >> 1, cl = ci & 1;
                atomicAdd(&scol[wn * 16 + nf * 8 + tq * 2 + cl], v);
            }
        }
    }
    __syncthreads();

    if (tid < NBT && srow[tid] != 0.f) atomicAdd(&g_neg_sum[i0 + tid], srow[tid]);
    if (dual && tid < NBT && scol[tid] != 0.f) atomicAdd(&g_neg_sum[j0 + tid], scol[tid]);
    if (tid == 0 && slast2[0] != 0.f) {
        atomicAdd(&g_last[2], slast2[0]);
        atomicAdd(&g_last[3], slast2[1]);
    }
}

// -----------------------------------------------------------------------------
// Kernel 3: finalize
// -----------------------------------------------------------------------------
__global__ void finalize(float* __restrict__ out, int n) {
    __shared__ float shl[8], shp[8];
    int tid = threadIdx.x;
    float loss = 0.f, noneg = 0.f;
    for (int i = tid; i < n; i += blockDim.x) {
        float ns = g_neg_sum[i];
        if (ns > 0.f) {
            loss += 0.5f * log1pf(g_pos_sum[i]) + (1.f / 50.f) * log1pf(ns);
        } else {
            noneg += 1.f;
        }
    }
    #pragma unroll
    for (int m = 16; m; m >>= 1) {
        loss  += __shfl_xor_sync(0xffffffffu, loss, m);
        noneg += __shfl_xor_sync(0xffffffffu, noneg, m);
    }
    int w = tid >> 5;
    if ((tid & 31) == 0) { shl[w] = loss; shp[w] = noneg; }
    __syncthreads();
    if (tid == 0) {
        float L = 0.f, P = 0.f;
        int nw = blockDim.x >> 5;
        for (int k = 0; k < nw; k++) { L += shl[k]; P += shp[k]; }
        out[0] = L / (float)n;
        out[1] = P / (float)n;
        out[2] = g_last[1] / fmaxf(g_last[0], 1.f);
        out[3] = g_last[3] / fmaxf(g_last[2], 1.f);
    }
}

// -----------------------------------------------------------------------------
extern "C" void kernel_launch(void* const* d_in, const int* in_sizes, int n_in,
                              void* d_out, int out_size) {
    const float* x = (const float*)d_in[0];
    const int*   t = (const int*)d_in[1];
    int n = in_sizes[1];
    int d = in_sizes[0] / n;
    float* out = (float*)d_out;

    int pos_smem = TJC * PPAD * (int)sizeof(float4);   // 101376 B

    static bool attr_done = false;
    if (!attr_done) {
        cudaFuncSetAttribute(pos_pass4, cudaFuncAttributeMaxDynamicSharedMemorySize, pos_smem);
        cudaFuncSetAttribute(neg_pass_mma, cudaFuncAttributeMaxDynamicSharedMemorySize, NEG_SMEM);
        attr_done = true;
    }

    k_prep<<<1, 1024>>>(t, n);
    k_split<<<(n * d + 255) / 256, 256>>>(x, n, n * d);

    pos_pass4<<<NCLS, 256, pos_smem>>>(x, n, d);

    dim3 grid2(n / NBT, n / NBT);
    neg_pass_mma<<<grid2, 256, NEG_SMEM>>>(t, n);

    finalize<<<1, 256>>>(out, n);
}

// round 17
// speedup vs baseline: 2.8694x; 1.1802x over previous
#include <cuda_runtime.h>
#include <cuda_bf16.h>
#include <cstdint>
#include <stdint.h>
#include <math.h>

#define NMAX 8192
#define DMAX 128
#define NCLS 128

// Scratch (no cudaMalloc allowed)
__device__ float g_pos_min[NMAX];
__device__ float g_pos_sum[NMAX];
__device__ float g_neg_sum[NMAX];
__device__ float g_last[4];       // [0]=pos_cnt [1]=pos_simsum [2]=neg_cnt [3]=neg_simsum
__device__ int   g_cls_off[NCLS + 1];
__device__ int   g_cls_list[NMAX];
__device__ __nv_bfloat16 g_xhi[NMAX * DMAX];
__device__ __nv_bfloat16 g_xlo[NMAX * DMAX];

// -----------------------------------------------------------------------------
// Setup kernel 1: fused hist -> scan -> scatter (single CTA)
// -----------------------------------------------------------------------------
__global__ __launch_bounds__(1024)
void k_prep(const int* __restrict__ t, int n) {
    __shared__ int scnt[NCLS];
    __shared__ int scur[NCLS];
    int tid = threadIdx.x;
    if (tid < NCLS) scnt[tid] = 0;
    if (tid < 4) g_last[tid] = 0.f;
    __syncthreads();
    for (int i = tid; i < n; i += blockDim.x) atomicAdd(&scnt[t[i]], 1);
    __syncthreads();
    if (tid == 0) {
        int acc = 0;
        for (int c = 0; c < NCLS; c++) { g_cls_off[c] = acc; scur[c] = acc; acc += scnt[c]; }
        g_cls_off[NCLS] = acc;
    }
    __syncthreads();
    for (int i = tid; i < n; i += blockDim.x) {
        int p = atomicAdd(&scur[t[i]], 1);
        g_cls_list[p] = i;
    }
}

// Setup kernel 2: bf16 split (4 elems/thread) + zero neg accumulators
__global__ void k_split(const float4* __restrict__ x4, int n4, int total4) {
    int i = blockIdx.x * blockDim.x + threadIdx.x;
    if (i < total4) {
        float4 v = x4[i];
        __nv_bfloat16 h0 = __float2bfloat16(v.x);
        __nv_bfloat16 h1 = __float2bfloat16(v.y);
        __nv_bfloat16 h2 = __float2bfloat16(v.z);
        __nv_bfloat16 h3 = __float2bfloat16(v.w);
        __nv_bfloat16 l0 = __float2bfloat16(v.x - __bfloat162float(h0));
        __nv_bfloat16 l1 = __float2bfloat16(v.y - __bfloat162float(h1));
        __nv_bfloat16 l2 = __float2bfloat16(v.z - __bfloat162float(h2));
        __nv_bfloat16 l3 = __float2bfloat16(v.w - __bfloat162float(h3));
        ushort4 hv, lv;
        hv.x = *(unsigned short*)&h0; hv.y = *(unsigned short*)&h1;
        hv.z = *(unsigned short*)&h2; hv.w = *(unsigned short*)&h3;
        lv.x = *(unsigned short*)&l0; lv.y = *(unsigned short*)&l1;
        lv.z = *(unsigned short*)&l2; lv.w = *(unsigned short*)&l3;
        *(ushort4*)(g_xhi + 4 * (size_t)i) = hv;
        *(ushort4*)(g_xlo + 4 * (size_t)i) = lv;
        if (i < n4) ((float4*)g_neg_sum)[i] = make_float4(0.f, 0.f, 0.f, 0.f);
    }
}

// -----------------------------------------------------------------------------
// ordered-uint float key helpers (for atomicMin on floats incl. negatives)
// -----------------------------------------------------------------------------
__device__ __forceinline__ unsigned fkey(float f) {
    unsigned u = __float_as_uint(f);
    return (u & 0x80000000u) ? ~u : (u | 0x80000000u);
}
__device__ __forceinline__ float fdec(unsigned k) {
    return (k & 0x80000000u) ? __uint_as_float(k ^ 0x80000000u)
                             : __uint_as_float(~k);
}

// -----------------------------------------------------------------------------
// Kernel 1: class-blocked positive pass (exact fp32), micro-tiled Gram.
// -----------------------------------------------------------------------------
#define TJC  192
#define PPAD 33

__global__ __launch_bounds__(256)
void pos_pass4(const float* __restrict__ x, int n, int d) {
    int cls = blockIdx.x;
    int beg = g_cls_off[cls], end = g_cls_off[cls + 1];
    int cnt = end - beg;
    if (cnt <= 0) return;

    extern __shared__ float4 sx[];
    __shared__ int      sidx[TJC];
    __shared__ unsigned skey[TJC];
    __shared__ float    spsum[TJC], spcnt[TJC], spsim[TJC];

    int tid = threadIdx.x, lane = tid & 31, wrp = tid >> 5;
    const float4* X4 = (const float4*)x;
    int d4 = d >> 2;

    if (cnt <= TJC && d4 == 32) {
        for (int m = tid; m < cnt; m += 256) {
            sidx[m] = g_cls_list[beg + m];
            skey[m] = 0xFF800000u;
            spsum[m] = 0.f; spcnt[m] = 0.f; spsim[m] = 0.f;
        }
        for (int idx = tid; idx < cnt * 32; idx += 256) {
            int r = idx >> 5, c = idx & 31;
            sx[r * PPAD + c] = X4[(size_t)g_cls_list[beg + r] * 32 + c];
        }
        __syncthreads();

        int nt = (cnt + 15) >> 4;
        int ntri = (nt * (nt + 1)) >> 1;
        int r8 = lane & 7, c8 = lane >> 3;

        for (int tt = wrp; tt < ntri; tt += 8) {
            int ti = 0, rem = tt;
            while (rem >= nt - ti) { rem -= nt - ti; ti++; }
            int tj = ti + rem;
            bool offd = (ti < tj);

            int ri0 = ti * 16 + r8;
            int ri1 = ri0 + 8;
            int cjb = tj * 16 + c8 * 4;

            const float4* a0p = sx + min(ri0, cnt - 1) * PPAD;
            const float4* a1p = sx + min(ri1, cnt - 1) * PPAD;
            const float4* b0p = sx + min(cjb + 0, cnt - 1) * PPAD;
            const float4* b1p = sx + min(cjb + 1, cnt - 1) * PPAD;
            const float4* b2p = sx + min(cjb + 2, cnt - 1) * PPAD;
            const float4* b3p = sx + min(cjb + 3, cnt - 1) * PPAD;

            float acc[2][4];
            #pragma unroll
            for (int a = 0; a < 2; a++)
                #pragma unroll
                for (int b = 0; b < 4; b++) acc[a][b] = 0.f;

            #pragma unroll 8
            for (int k = 0; k < 32; k++) {
                float4 a0 = a0p[k], a1 = a1p[k];
                float4 b0 = b0p[k], b1 = b1p[k], b2 = b2p[k], b3 = b3p[k];
                acc[0][0] += a0.x*b0.x + a0.y*b0.y + a0.z*b0.z + a0.w*b0.w;
                acc[0][1] += a0.x*b1.x + a0.y*b1.y + a0.z*b1.z + a0.w*b1.w;
                acc[0][2] += a0.x*b2.x + a0.y*b2.y + a0.z*b2.z + a0.w*b2.w;
                acc[0][3] += a0.x*b3.x + a0.y*b3.y + a0.z*b3.z + a0.w*b3.w;
                acc[1][0] += a1.x*b0.x + a1.y*b0.y + a1.z*b0.z + a1.w*b0.w;
                acc[1][1] += a1.x*b1.x + a1.y*b1.y + a1.z*b1.z + a1.w*b1.w;
                acc[1][2] += a1.x*b2.x + a1.y*b2.y + a1.z*b2.z + a1.w*b2.w;
                acc[1][3] += a1.x*b3.x + a1.y*b3.y + a1.z*b3.z + a1.w*b3.w;
            }

            float rowE[2] = {0.f, 0.f}, rowC[2] = {0.f, 0.f}, rowS[2] = {0.f, 0.f};
            unsigned rowK[2] = {0xFF800000u, 0xFF800000u};
            float colE[4] = {0.f,0.f,0.f,0.f}, colC[4] = {0.f,0.f,0.f,0.f}, colS[4] = {0.f,0.f,0.f,0.f};
            unsigned colK[4] = {0xFF800000u,0xFF800000u,0xFF800000u,0xFF800000u};

            #pragma unroll
            for (int rr = 0; rr < 2; rr++) {
                int ri = rr ? ri1 : ri0;
                bool vr = (ri < cnt);
                #pragma unroll
                for (int jj = 0; jj < 4; jj++) {
                    float s = acc[rr][jj];
                    if (vr && (cjb + jj) < cnt && s < 0.9f) {
                        float dm = s - 0.9f;
                        float e = expf(-2.f * (s - 0.5f) + dm * dm);
                        unsigned kk = fkey(s);
                        rowE[rr] += e; rowC[rr] += 1.f; rowS[rr] += s;
                        rowK[rr] = min(rowK[rr], kk);
                        if (offd) {
                            colE[jj] += e; colC[jj] += 1.f; colS[jj] += s;
                            colK[jj] = min(colK[jj], kk);
                        }
                    }
                }
            }

            #pragma unroll
            for (int rr = 0; rr < 2; rr++) {
                rowE[rr] += __shfl_xor_sync(0xffffffffu, rowE[rr], 8);
                rowC[rr] += __shfl_xor_sync(0xffffffffu, rowC[rr], 8);
                rowS[rr] += __shfl_xor_sync(0xffffffffu, rowS[rr], 8);
                rowK[rr] = min(rowK[rr], __shfl_xor_sync(0xffffffffu, rowK[rr], 8));
                rowE[rr] += __shfl_xor_sync(0xffffffffu, rowE[rr], 16);
                rowC[rr] += __shfl_xor_sync(0xffffffffu, rowC[rr], 16);
                rowS[rr] += __shfl_xor_sync(0xffffffffu, rowS[rr], 16);
                rowK[rr] = min(rowK[rr], __shfl_xor_sync(0xffffffffu, rowK[rr], 16));
                int ri = rr ? ri1 : ri0;
                if (c8 == 0 && ri < cnt && rowC[rr] > 0.f) {
                    atomicAdd(&spsum[ri], rowE[rr]);
                    atomicAdd(&spcnt[ri], rowC[rr]);
                    atomicAdd(&spsim[ri], rowS[rr]);
                    atomicMin(&skey[ri], rowK[rr]);
                }
            }
            if (offd) {
                #pragma unroll
                for (int jj = 0; jj < 4; jj++) {
                    colE[jj] += __shfl_xor_sync(0xffffffffu, colE[jj], 1);
                    colC[jj] += __shfl_xor_sync(0xffffffffu, colC[jj], 1);
                    colS[jj] += __shfl_xor_sync(0xffffffffu, colS[jj], 1);
                    colK[jj] = min(colK[jj], __shfl_xor_sync(0xffffffffu, colK[jj], 1));
                    colE[jj] += __shfl_xor_sync(0xffffffffu, colE[jj], 2);
                    colC[jj] += __shfl_xor_sync(0xffffffffu, colC[jj], 2);
                    colS[jj] += __shfl_xor_sync(0xffffffffu, colS[jj], 2);
                    colK[jj] = min(colK[jj], __shfl_xor_sync(0xffffffffu, colK[jj], 2));
                    colE[jj] += __shfl_xor_sync(0xffffffffu, colE[jj], 4);
                    colC[jj] += __shfl_xor_sync(0xffffffffu, colC[jj], 4);
                    colS[jj] += __shfl_xor_sync(0xffffffffu, colS[jj], 4);
                    colK[jj] = min(colK[jj], __shfl_xor_sync(0xffffffffu, colK[jj], 4));
                    int cj = cjb + jj;
                    if (r8 == 0 && cj < cnt && colC[jj] > 0.f) {
                        atomicAdd(&spsum[cj], colE[jj]);
                        atomicAdd(&spcnt[cj], colC[jj]);
                        atomicAdd(&spsim[cj], colS[jj]);
                        atomicMin(&skey[cj], colK[jj]);
                    }
                }
            }
        }
        __syncthreads();

        for (int m = tid; m < cnt; m += 256) {
            int i = sidx[m];
            g_pos_min[i] = fdec(skey[m]);
            g_pos_sum[i] = spsum[m];
            if (i == n - 1) { g_last[0] = spcnt[m]; g_last[1] = spsim[m]; }
        }
    } else {
        for (int mi = wrp; mi < cnt; mi += 8) {
            int i = g_cls_list[beg + mi];
            float pmin = INFINITY, psum = 0.f, pcnt = 0.f, psim = 0.f;
            for (int mj = lane; mj < cnt; mj += 32) {
                const float4* xi = X4 + (size_t)i * d4;
                const float4* xj = X4 + (size_t)g_cls_list[beg + mj] * d4;
                float s = 0.f;
                for (int k = 0; k < d4; k++) {
                    float4 a = xi[k], b = xj[k];
                    s += a.x*b.x + a.y*b.y + a.z*b.z + a.w*b.w;
                }
                if (s < 0.9f) {
                    pmin = fminf(pmin, s);
                    float dm = s - 0.9f;
                    psum += expf(-2.f * (s - 0.5f) + dm * dm);
                    pcnt += 1.f;
                    psim += s;
                }
            }
            #pragma unroll
            for (int m = 16; m; m >>= 1) {
                pmin = fminf(pmin, __shfl_xor_sync(0xffffffffu, pmin, m));
                psum += __shfl_xor_sync(0xffffffffu, psum, m);
                pcnt += __shfl_xor_sync(0xffffffffu, pcnt, m);
                psim += __shfl_xor_sync(0xffffffffu, psim, m);
            }
            if (lane == 0) {
                g_pos_min[i] = pmin;
                g_pos_sum[i] = psum;
                if (i == n - 1) { g_last[0] = pcnt; g_last[1] = psim; }
            }
        }
    }
}

// -----------------------------------------------------------------------------
// Kernel 1b: last-row neg stats (exact fp32). Runs after pos_pass4.
// -----------------------------------------------------------------------------
__global__ __launch_bounds__(256)
void last_row(const float* __restrict__ x, const int* __restrict__ t, int n, int d) {
    __shared__ float4 sxl[32];
    int d4 = d >> 2;
    bool fast = (d4 == 32);
    if (fast && threadIdx.x < 32)
        sxl[threadIdx.x] = ((const float4*)x)[(size_t)(n - 1) * 32 + threadIdx.x];
    __syncthreads();

    int j = blockIdx.x * blockDim.x + threadIdx.x;
    int tl = t[n - 1];
    float pm = g_pos_min[n - 1];
    float thr = fmaxf(0.1f, pm - 0.5f);

    float c = 0.f, ss = 0.f;
    if (j < n && t[j] != tl) {
        const float4* xj = (const float4*)x + (size_t)j * d4;
        float s0 = 0.f, s1 = 0.f, s2 = 0.f, s3 = 0.f;
        if (fast) {
            #pragma unroll 8
            for (int k = 0; k < 32; k += 4) {
                float4 a0 = sxl[k], b0 = xj[k];
                float4 a1 = sxl[k+1], b1 = xj[k+1];
                float4 a2 = sxl[k+2], b2 = xj[k+2];
                float4 a3 = sxl[k+3], b3 = xj[k+3];
                s0 += a0.x*b0.x + a0.y*b0.y + a0.z*b0.z + a0.w*b0.w;
                s1 += a1.x*b1.x + a1.y*b1.y + a1.z*b1.z + a1.w*b1.w;
                s2 += a2.x*b2.x + a2.y*b2.y + a2.z*b2.z + a2.w*b2.w;
                s3 += a3.x*b3.x + a3.y*b3.y + a3.z*b3.z + a3.w*b3.w;
            }
        } else {
            const float4* xl = (const float4*)x + (size_t)(n - 1) * d4;
            for (int k = 0; k < d4; k++) {
                float4 a = xl[k], b = xj[k];
                s0 += a.x*b.x + a.y*b.y + a.z*b.z + a.w*b.w;
            }
        }
        float s = (s0 + s1) + (s2 + s3);
        if (s > thr) { c = 1.f; ss = s; }
    }
    #pragma unroll
    for (int m = 16; m; m >>= 1) {
        c  += __shfl_xor_sync(0xffffffffu, c, m);
        ss += __shfl_xor_sync(0xffffffffu, ss, m);
    }
    if ((threadIdx.x & 31) == 0 && c != 0.f) {
        atomicAdd(&g_last[2], c);
        atomicAdd(&g_last[3], ss);
    }
}

// -----------------------------------------------------------------------------
// Kernel 2: 128x64-tile HMMA (bf16-split), ldmatrix, occ 2, triangular 1D grid.
// dual (j0 >= i0+128): credit both directions; straddle: row only.
// Gates folded: thr = max(0.1, pmin-0.5); exp arg = fma(s, s+49.8, -24.99).
// -----------------------------------------------------------------------------
#define BM 128
#define BN 64
#define PAD 136
#define ROWB (PAD * 2)
#define A_TILE (BM * ROWB)
#define B_TILE (BN * ROWB)
#define NEG_SMEM (2 * A_TILE + 2 * B_TILE)
#define FRAG16 (16 * ROWB)

__device__ __forceinline__ uint32_t smem_u32(const void* p) {
    uint32_t a;
    asm("{ .reg .u64 t; cvta.to.shared.u64 t, %1; cvt.u32.u64 %0, t; }"
        : "=r"(a) : "l"(p));
    return a;
}
__device__ __forceinline__ void cp_async16(uint32_t dst, const void* src) {
    asm volatile("cp.async.cg.shared.global [%0], [%1], 16;" :: "r"(dst), "l"(src));
}
__device__ __forceinline__ void ldsm4(unsigned* r, uint32_t addr) {
    asm volatile("ldmatrix.sync.aligned.m8n8.x4.shared.b16 {%0,%1,%2,%3}, [%4];"
                 : "=r"(r[0]), "=r"(r[1]), "=r"(r[2]), "=r"(r[3]) : "r"(addr));
}
__device__ __forceinline__ void mma16816(float* c, const unsigned* a, const unsigned* b) {
    asm volatile(
        "mma.sync.aligned.m16n8k16.row.col.f32.bf16.bf16.f32 "
        "{%0,%1,%2,%3}, {%4,%5,%6,%7}, {%8,%9}, {%0,%1,%2,%3};"
        : "+f"(c[0]), "+f"(c[1]), "+f"(c[2]), "+f"(c[3])
        : "r"(a[0]), "r"(a[1]), "r"(a[2]), "r"(a[3]), "r"(b[0]), "r"(b[1]));
}

__global__ __launch_bounds__(256, 2)
void neg_pass_mma(const int* __restrict__ t, int n) {
    // triangular decode: row ib (BM band), col jt (BN tile), jt >= 2*ib
    int tt = blockIdx.x;
    int K = (n / BN) + 1;
    float disc = (float)K * (float)K - 4.f * (float)tt;
    int ib = (int)(((float)K - sqrtf(disc)) * 0.5f);
    if (ib < 0) ib = 0;
    while (ib > 0 && ib * (K - ib) > tt) ib--;
    while ((ib + 1) * (K - ib - 1) <= tt) ib++;
    int jt = 2 * ib + (tt - ib * (K - ib));

    int i0 = ib * BM, j0 = jt * BN;
    bool dual = (jt >= 2 * ib + 2);

    extern __shared__ char dsm[];
    uint32_t base = smem_u32(dsm);
    uint32_t Ahi = base, Alo = base + A_TILE;
    uint32_t Bhi = base + 2 * A_TILE, Blo = base + 2 * A_TILE + B_TILE;

    __shared__ float srow[BM], scol[BN];

    int tid  = threadIdx.x;
    int lane = tid & 31;
    int w    = tid >> 5;
    int wm   = w >> 1;                   // 0..3 -> 32-row strip
    int wn   = w & 1;                    // 0..1 -> 32-col strip
    int q    = lane >> 2;                // 0..7
    int tq   = lane & 3;                 // 0..3

    if (tid < BM) srow[tid] = 0.f;
    if (tid < BN) scol[tid] = 0.f;

    for (int idx = tid; idx < BM * 16; idx += 256) {
        int r = idx >> 4, ch = idx & 15;
        uint32_t off = (uint32_t)r * ROWB + (uint32_t)ch * 16u;
        cp_async16(Ahi + off, (const char*)(g_xhi + (size_t)(i0 + r) * DMAX) + ch * 16);
        cp_async16(Alo + off, (const char*)(g_xlo + (size_t)(i0 + r) * DMAX) + ch * 16);
    }
    for (int idx = tid; idx < BN * 16; idx += 256) {
        int r = idx >> 4, ch = idx & 15;
        uint32_t off = (uint32_t)r * ROWB + (uint32_t)ch * 16u;
        cp_async16(Bhi + off, (const char*)(g_xhi + (size_t)(j0 + r) * DMAX) + ch * 16);
        cp_async16(Blo + off, (const char*)(g_xlo + (size_t)(j0 + r) * DMAX) + ch * 16);
    }
    asm volatile("cp.async.commit_group;" ::: "memory");

    // labels + folded gate thresholds while loads fly
    int   tti[4]; float thrR[4];
    int   ttj[8]; float thrC[8];
    #pragma unroll
    for (int mf = 0; mf < 2; mf++)
        #pragma unroll
        for (int rh = 0; rh < 2; rh++) {
            int row = i0 + wm * 32 + mf * 16 + q + rh * 8;
            tti[mf * 2 + rh]  = t[row];
            thrR[mf * 2 + rh] = fmaxf(0.1f, g_pos_min[row] - 0.5f);
        }
    #pragma unroll
    for (int nf = 0; nf < 4; nf++)
        #pragma unroll
        for (int cl = 0; cl < 2; cl++) {
            int col = j0 + wn * 32 + nf * 8 + tq * 2 + cl;
            ttj[nf * 2 + cl]  = t[col];
            thrC[nf * 2 + cl] = fmaxf(0.1f, g_pos_min[col] - 0.5f);
        }

    uint32_t aoff = (uint32_t)(wm * 32 + (lane & 15)) * ROWB
                  + ((lane >> 4) & 1) * 16u;
    uint32_t boff = (uint32_t)(wn * 32 + (lane & 7) + ((lane >> 4) & 1) * 8) * ROWB
                  + ((lane >> 3) & 1) * 16u;

    asm volatile("cp.async.wait_group 0;" ::: "memory");
    __syncthreads();

    // ---- MMA: 3 bf16-split products ----
    float acc[2][4][4];
    #pragma unroll
    for (int mf = 0; mf < 2; mf++)
        #pragma unroll
        for (int nf = 0; nf < 4; nf++)
            #pragma unroll
            for (int r = 0; r < 4; r++) acc[mf][nf][r] = 0.f;

    #pragma unroll
    for (int kc = 0; kc < DMAX / 16; kc++) {
        uint32_t kb = (uint32_t)kc * 32u;
        unsigned ah[2][4], al[2][4], bh[4][2], bl[4][2];
        ldsm4(ah[0], Ahi + aoff + kb);
        ldsm4(ah[1], Ahi + aoff + FRAG16 + kb);
        ldsm4(al[0], Alo + aoff + kb);
        ldsm4(al[1], Alo + aoff + FRAG16 + kb);
        ldsm4(&bh[0][0], Bhi + boff + kb);
        ldsm4(&bh[2][0], Bhi + boff + FRAG16 + kb);
        ldsm4(&bl[0][0], Blo + boff + kb);
        ldsm4(&bl[2][0], Blo + boff + FRAG16 + kb);
        #pragma unroll
        for (int mf = 0; mf < 2; mf++)
            #pragma unroll
            for (int nf = 0; nf < 4; nf++) {
                mma16816(acc[mf][nf], ah[mf], bh[nf]);   // hi*hi
                mma16816(acc[mf][nf], ah[mf], bl[nf]);   // hi*lo
                mma16816(acc[mf][nf], al[mf], bh[nf]);   // lo*hi
            }
    }

    // ---- epilogue ----
    float rsum[4], csum[8];
    #pragma unroll
    for (int k = 0; k < 4; k++) rsum[k] = 0.f;
    #pragma unroll
    for (int k = 0; k < 8; k++) csum[k] = 0.f;

    #pragma unroll
    for (int mf = 0; mf < 2; mf++) {
        #pragma unroll
        for (int nf = 0; nf < 4; nf++) {
            #pragma unroll
            for (int r = 0; r < 4; r++) {
                float s = acc[mf][nf][r];
                int ri = mf * 2 + (r >> 1);
                int ci = nf * 2 + (r & 1);
                if (ttj[ci] != tti[ri] && s > 0.1f) {
                    // 50(s-0.5) + (0.1-s)^2 == s^2 + 49.8 s - 24.99
                    float e = __expf(fmaf(s, s + 49.8f, -24.99f));
                    if (s > thrR[ri]) rsum[ri] += e;
                    if (dual & (s > thrC[ci])) csum[ci] += e;
                }
            }
        }
    }

    // row sums: reduce over tq (xor 1,2)
    #pragma unroll
    for (int ri = 0; ri < 4; ri++) {
        float v = rsum[ri];
        v += __shfl_xor_sync(0xffffffffu, v, 1);
        v += __shfl_xor_sync(0xffffffffu, v, 2);
        if (tq == 0 && v != 0.f) {
            int mf = ri >> 1, rh = ri & 1;
            atomicAdd(&srow[wm * 32 + mf * 16 + q + rh * 8], v);
        }
    }
    // col sums: reduce over q (xor 4,8,16)
    if (dual) {
        #pragma unroll
        for (int ci = 0; ci < 8; ci++) {
            float v = csum[ci];
            v += __shfl_xor_sync(0xffffffffu, v, 4);
            v += __shfl_xor_sync(0xffffffffu, v, 8);
            v += __shfl_xor_sync(0xffffffffu, v, 16);
            if (q == 0 && v != 0.f) {
                int nf = ci >> 1, cl = ci & 1;
                atomicAdd(&scol[wn * 32 + nf * 8 + tq * 2 + cl], v);
            }
        }
    }
    __syncthreads();

    if (tid < BM && srow[tid] != 0.f) atomicAdd(&g_neg_sum[i0 + tid], srow[tid]);
    if (dual && tid < BN && scol[tid] != 0.f) atomicAdd(&g_neg_sum[j0 + tid], scol[tid]);
}

// -----------------------------------------------------------------------------
// Kernel 3: finalize
// -----------------------------------------------------------------------------
__global__ void finalize(float* __restrict__ out, int n) {
    __shared__ float shl[8], shp[8];
    int tid = threadIdx.x;
    float loss = 0.f, noneg = 0.f;
    for (int i = tid; i < n; i += blockDim.x) {
        float ns = g_neg_sum[i];
        if (ns > 0.f) {
            loss += 0.5f * log1pf(g_pos_sum[i]) + (1.f / 50.f) * log1pf(ns);
        } else {
            noneg += 1.f;
        }
    }
    #pragma unroll
    for (int m = 16; m; m >>= 1) {
        loss  += __shfl_xor_sync(0xffffffffu, loss, m);
        noneg += __shfl_xor_sync(0xffffffffu, noneg, m);
    }
    int w = tid >> 5;
    if ((tid & 31) == 0) { shl[w] = loss; shp[w] = noneg; }
    __syncthreads();
    if (tid == 0) {
        float L = 0.f, P = 0.f;
        int nw = blockDim.x >> 5;
        for (int k = 0; k < nw; k++) { L += shl[k]; P += shp[k]; }
        out[0] = L / (float)n;
        out[1] = P / (float)n;
        out[2] = g_last[1] / fmaxf(g_last[0], 1.f);
        out[3] = g_last[3] / fmaxf(g_last[2], 1.f);
    }
}

// -----------------------------------------------------------------------------
extern "C" void kernel_launch(void* const* d_in, const int* in_sizes, int n_in,
                              void* d_out, int out_size) {
    const float* x = (const float*)d_in[0];
    const int*   t = (const int*)d_in[1];
    int n = in_sizes[1];
    int d = in_sizes[0] / n;
    float* out = (float*)d_out;

    int pos_smem = TJC * PPAD * (int)sizeof(float4);

    static bool attr_done = false;
    if (!attr_done) {
        cudaFuncSetAttribute(pos_pass4, cudaFuncAttributeMaxDynamicSharedMemorySize, pos_smem);
        cudaFuncSetAttribute(neg_pass_mma, cudaFuncAttributeMaxDynamicSharedMemorySize, NEG_SMEM);
        attr_done = true;
    }

    k_prep<<<1, 1024>>>(t, n);
    k_split<<<((n * d / 4) + 255) / 256, 256>>>((const float4*)x, n / 4, n * d / 4);

    pos_pass4<<<NCLS, 256, pos_smem>>>(x, n, d);
    last_row<<<(n + 255) / 256, 256>>>(x, t, n, d);

    int ntb = n / BM;
    int ntri = ntb * ((n / BN) - ntb + 1);
    neg_pass_mma<<<ntri, 256, NEG_SMEM>>>(t, n);

    finalize<<<1, 256>>>(out, n);
}